// round 11
// baseline (speedup 1.0000x reference)
#include <cuda_runtime.h>

#define NT_MAX 200000
#define ETT_MAX 1100000

typedef unsigned int uint32;

// ---------------------------------------------------------------------------
// Scratch (__device__ globals — allocation-free rule)
// ---------------------------------------------------------------------------
__device__ float g_agg  [NT_MAX * 5];
__device__ float g_fused[NT_MAX * 64];
__device__ float g_Bdep [NT_MAX * 64];
__device__ float g_Cdep [NT_MAX * 64];
__device__ float g_Brev [NT_MAX * 64];
__device__ float g_Crev [NT_MAX * 64];
__device__ int   g_degD [NT_MAX];
__device__ int   g_degR [NT_MAX];
__device__ int   g_ptrD [NT_MAX + 1];
__device__ int   g_ptrR [NT_MAX + 1];
__device__ int   g_curD [NT_MAX];
__device__ int   g_curR [NT_MAX];
__device__ int   g_srcD [ETT_MAX];
__device__ int   g_srcR [ETT_MAX];
__device__ int   g_bsumD[512];
__device__ int   g_bsumR[512];
__device__ float g_colsum[64];

__device__ __forceinline__ float leaky(float x) { return x > 0.f ? x : 0.01f * x; }

__device__ __forceinline__ float warp_sum(float v) {
#pragma unroll
    for (int o = 16; o > 0; o >>= 1) v += __shfl_xor_sync(0xffffffffu, v, o);
    return v;
}

// ---- tf32 helpers ---------------------------------------------------------
__device__ __forceinline__ uint32 tf32_of(float x) {
    uint32 u;
    asm("cvt.rna.tf32.f32 %0, %1;" : "=r"(u) : "f"(x));
    return u;
}
__device__ __forceinline__ void split_tf32(float x, uint32& hi, uint32& lo) {
    hi = tf32_of(x);
    lo = tf32_of(x - __uint_as_float(hi));
}
__device__ __forceinline__ void mma_tf32(float4& d,
                                         uint32 a0, uint32 a1, uint32 a2, uint32 a3,
                                         uint32 b0, uint32 b1) {
    asm("mma.sync.aligned.m16n8k8.row.col.f32.tf32.tf32.f32 "
        "{%0,%1,%2,%3},{%4,%5,%6,%7},{%8,%9},{%0,%1,%2,%3};"
        : "+f"(d.x), "+f"(d.y), "+f"(d.z), "+f"(d.w)
        : "r"(a0), "r"(a1), "r"(a2), "r"(a3), "r"(b0), "r"(b1));
}

// ---------------------------------------------------------------------------
// K0: zero accumulators
// ---------------------------------------------------------------------------
__global__ void k_zero(int n) {
    int i = blockIdx.x * blockDim.x + threadIdx.x;
    if (i < n * 5) g_agg[i] = 0.f;
    if (i < n) { g_degD[i] = 0; g_degR[i] = 0; }
    if (i < 64) g_colsum[i] = 0.f;
}

// ---------------------------------------------------------------------------
// K1: data->task scatter-add + tt degree histograms (fused)
// ---------------------------------------------------------------------------
__global__ void k_edges_pre(const float* __restrict__ data_x,
                            const int* __restrict__ dsrc, const int* __restrict__ ddst,
                            int e_dt,
                            const int* __restrict__ tsrc, const int* __restrict__ tdst,
                            int e_tt) {
    int e = blockIdx.x * blockDim.x + threadIdx.x;
    if (e < e_dt) {
        int s = __ldg(&dsrc[e]);
        int d = __ldg(&ddst[e]);
        const float* xr = data_x + s * 5;
        float* ar = g_agg + d * 5;
#pragma unroll
        for (int k = 0; k < 5; k++) atomicAdd(ar + k, __ldg(&xr[k]));
    }
    if (e < e_tt) {
        atomicAdd(&g_degD[__ldg(&tdst[e])], 1);
        atomicAdd(&g_degR[__ldg(&tsrc[e])], 1);
    }
}

// ---------------------------------------------------------------------------
// Scan stage 1
// ---------------------------------------------------------------------------
__global__ __launch_bounds__(256) void k_scan_blk(int n) {
    int arr = blockIdx.y;
    const int* deg = arr ? g_degR : g_degD;
    int* ptr = arr ? g_ptrR : g_ptrD;
    int* bsum = arr ? g_bsumR : g_bsumD;
    __shared__ int sh[256];
    int tid = threadIdx.x;
    int base = blockIdx.x * 1024;
    int v[4]; int s = 0;
#pragma unroll
    for (int j = 0; j < 4; j++) {
        int idx = base + tid * 4 + j;
        v[j] = (idx < n) ? deg[idx] : 0;
        s += v[j];
    }
    sh[tid] = s;
    __syncthreads();
#pragma unroll
    for (int d = 1; d < 256; d <<= 1) {
        int t = 0;
        if (tid >= d) t = sh[tid - d];
        __syncthreads();
        sh[tid] += t;
        __syncthreads();
    }
    int off = sh[tid] - s;
#pragma unroll
    for (int j = 0; j < 4; j++) {
        int idx = base + tid * 4 + j;
        if (idx < n) ptr[idx] = off;
        off += v[j];
    }
    if (tid == 0) bsum[blockIdx.x] = sh[255];
}

// ---------------------------------------------------------------------------
// Scan stage 2: warp-parallel scan of block sums (one warp per array)
// ---------------------------------------------------------------------------
__global__ void k_scan_top(int nblk) {
    int lane = threadIdx.x & 31;
    int* bs = (threadIdx.x < 32) ? g_bsumD : g_bsumR;
    int base = 0;
    for (int i0 = 0; i0 < nblk; i0 += 32) {
        int idx = i0 + lane;
        int v = (idx < nblk) ? bs[idx] : 0;
        int incl = v;
#pragma unroll
        for (int o = 1; o < 32; o <<= 1) {
            int t = __shfl_up_sync(0xffffffffu, incl, o);
            if (lane >= o) incl += t;
        }
        if (idx < nblk) bs[idx] = base + incl - v;
        base += __shfl_sync(0xffffffffu, incl, 31);
    }
}

// ---------------------------------------------------------------------------
// Scan stage 3
// ---------------------------------------------------------------------------
__global__ __launch_bounds__(256) void k_scan_fix(int n, int E) {
    int arr = blockIdx.y;
    int* ptr = arr ? g_ptrR : g_ptrD;
    int* cur = arr ? g_curR : g_curD;
    const int* bsum = arr ? g_bsumR : g_bsumD;
    int off = bsum[blockIdx.x];
    int base = blockIdx.x * 1024 + threadIdx.x * 4;
#pragma unroll
    for (int j = 0; j < 4; j++) {
        int idx = base + j;
        if (idx < n) { int v = ptr[idx] + off; ptr[idx] = v; cur[idx] = v; }
    }
    if (blockIdx.x == 0 && threadIdx.x == 0) ptr[n] = E;
}

// ---------------------------------------------------------------------------
// K1c: scatter edges into CSR
// ---------------------------------------------------------------------------
__global__ void k_scatter(const int* __restrict__ tsrc, const int* __restrict__ tdst, int E) {
    int e = blockIdx.x * blockDim.x + threadIdx.x;
    if (e >= E) return;
    int s = __ldg(&tsrc[e]);
    int d = __ldg(&tdst[e]);
    int p = atomicAdd(&g_curD[d], 1);
    g_srcD[p] = s;
    int q = atomicAdd(&g_curR[s], 1);
    g_srcR[q] = d;
}

// ---------------------------------------------------------------------------
// K2: fused = leaky(LN(agg @ Wrel + brel + tasks @ Wroot))   (warp per row)
// ---------------------------------------------------------------------------
__global__ void k_fused(const float* __restrict__ tasks_x,
                        const float* __restrict__ Wrel, const float* __restrict__ brel,
                        const float* __restrict__ Wroot,
                        const float* __restrict__ lng, const float* __restrict__ lnb,
                        int n) {
    int gt = blockIdx.x * blockDim.x + threadIdx.x;
    int r = gt >> 5, lane = gt & 31;
    if (r >= n) return;
    float p0 = __ldg(&brel[lane]);
    float p1 = __ldg(&brel[lane + 32]);
    const float* ar = g_agg + r * 5;
#pragma unroll
    for (int k = 0; k < 5; k++) {
        float a = ar[k];
        p0 += a * __ldg(&Wrel[k * 64 + lane]);
        p1 += a * __ldg(&Wrel[k * 64 + lane + 32]);
    }
    const float* tr = tasks_x + r * 12;
#pragma unroll
    for (int k = 0; k < 12; k++) {
        float t = __ldg(&tr[k]);
        p0 += t * __ldg(&Wroot[k * 64 + lane]);
        p1 += t * __ldg(&Wroot[k * 64 + lane + 32]);
    }
    float m = warp_sum(p0 + p1) * (1.f / 64.f);
    float d0 = p0 - m, d1 = p1 - m;
    float v = warp_sum(d0 * d0 + d1 * d1) * (1.f / 64.f);
    float inv = rsqrtf(v + 1e-5f);
    float y0 = leaky(d0 * inv * __ldg(&lng[lane])      + __ldg(&lnb[lane]));
    float y1 = leaky(d1 * inv * __ldg(&lng[lane + 32]) + __ldg(&lnb[lane + 32]));
    g_fused[r * 64 + lane]      = y0;
    g_fused[r * 64 + lane + 32] = y1;
}

// ---------------------------------------------------------------------------
// K3: tensor-core B/C GEMMs (3xTF32, on-the-fly split), both convs, one launch.
// Block = 128 rows, 256 threads. Warp: m0=(wid&3)*32 rows, nhalf=(wid>>2)*64.
// smem floats: Xs [128][68]=8704 | WsD [64][136]=8704 | WsR 8704  (104 KB)
// ---------------------------------------------------------------------------
__global__ __launch_bounds__(256, 2) void k_gemm_tc(
    const float* __restrict__ depW1, const float* __restrict__ revW1, int n) {
    extern __shared__ float sm[];
    float* Xs  = sm;            // [128][68]
    float* WsD = sm + 8704;     // [64][136]
    float* WsR = sm + 17408;    // [64][136]
    int tid = threadIdx.x;
    int row0 = blockIdx.x * 128;

    for (int idx = tid; idx < 8192; idx += 256) {
        int k = idx >> 7, j = idx & 127;
        float wBd = depW1[(64 + k) * 64 + (j & 63)];
        WsD[k * 136 + j] = (j < 64) ? wBd : (depW1[k * 64 + (j - 64)] - wBd);
        float wBr = revW1[(64 + k) * 64 + (j & 63)];
        WsR[k * 136 + j] = (j < 64) ? wBr : (revW1[k * 64 + (j - 64)] - wBr);
    }
#pragma unroll
    for (int it = 0; it < 8; it++) {
        int fi = tid + it * 256;
        int r = fi >> 4, c4 = (fi & 15) * 4;
        float4 v = make_float4(0.f, 0.f, 0.f, 0.f);
        int row = row0 + r;
        if (row < n) v = *reinterpret_cast<const float4*>(&g_fused[row * 64 + c4]);
        *reinterpret_cast<float4*>(&Xs[r * 68 + c4]) = v;
    }
    __syncthreads();

    int lane = tid & 31, wid = tid >> 5;
    int gid = lane >> 2, tig = lane & 3;
    int m0 = (wid & 3) * 32;
    int nhalf = (wid >> 2) * 64;

#pragma unroll 1
    for (int conv = 0; conv < 2; conv++) {
        const float* Ws = conv ? WsR : WsD;
        float4 acc[2][8];
#pragma unroll
        for (int mt = 0; mt < 2; mt++)
#pragma unroll
            for (int nt = 0; nt < 8; nt++) acc[mt][nt] = make_float4(0.f, 0.f, 0.f, 0.f);

#pragma unroll
        for (int ks = 0; ks < 8; ks++) {
            int kb = ks * 8;
            uint32 ah[2][4], al[2][4];
#pragma unroll
            for (int mt = 0; mt < 2; mt++) {
                int rb = m0 + mt * 16;
                split_tf32(Xs[(rb + gid) * 68 + kb + tig],     ah[mt][0], al[mt][0]);
                split_tf32(Xs[(rb + gid + 8) * 68 + kb + tig], ah[mt][1], al[mt][1]);
                split_tf32(Xs[(rb + gid) * 68 + kb + tig + 4],     ah[mt][2], al[mt][2]);
                split_tf32(Xs[(rb + gid + 8) * 68 + kb + tig + 4], ah[mt][3], al[mt][3]);
            }
#pragma unroll
            for (int nt = 0; nt < 8; nt++) {
                int nc = nhalf + nt * 8 + gid;
                uint32 bh0, bl0, bh1, bl1;
                split_tf32(Ws[(kb + tig) * 136 + nc],     bh0, bl0);
                split_tf32(Ws[(kb + tig + 4) * 136 + nc], bh1, bl1);
#pragma unroll
                for (int mt = 0; mt < 2; mt++) {
                    mma_tf32(acc[mt][nt], ah[mt][0], ah[mt][1], ah[mt][2], ah[mt][3], bh0, bh1);
                    mma_tf32(acc[mt][nt], ah[mt][0], ah[mt][1], ah[mt][2], ah[mt][3], bl0, bl1);
                    mma_tf32(acc[mt][nt], al[mt][0], al[mt][1], al[mt][2], al[mt][3], bh0, bh1);
                }
            }
        }

        float* O = (nhalf == 0) ? (conv ? g_Brev : g_Bdep) : (conv ? g_Crev : g_Cdep);
#pragma unroll
        for (int mt = 0; mt < 2; mt++) {
#pragma unroll
            for (int nt = 0; nt < 8; nt++) {
                int c = nt * 8 + tig * 2;
                int rowA = row0 + m0 + mt * 16 + gid;
                int rowB = rowA + 8;
                if (rowA < n)
                    *reinterpret_cast<float2*>(&O[rowA * 64 + c]) =
                        make_float2(acc[mt][nt].x, acc[mt][nt].y);
                if (rowB < n)
                    *reinterpret_cast<float2*>(&O[rowB * 64 + c]) =
                        make_float2(acc[mt][nt].z, acc[mt][nt].w);
            }
        }
    }
}

// ---------------------------------------------------------------------------
// K5: tail with FUSED edge aggregation (no S arrays, no k_agg launch).
// Block = 128 rows, 256 threads, warp = 16 rows.
// Per stage: warp aggregates its 16 nodes' edges into Xs (smem), then TC GEMM
// (3xTF32 on-the-fly split), bias via deg, LN, then proj + reduce.
// smem floats: W [128][72] | Xs [128][68] | Dp | Rv | V 576 | CP 512 | DG 256
//   = 36672 floats = 146688 B
// ---------------------------------------------------------------------------
#define TS 68

__global__ __launch_bounds__(256) void k_tail2(
    const float* __restrict__ depb1, const float* __restrict__ depW2,
    const float* __restrict__ depb2,
    const float* __restrict__ depg,  const float* __restrict__ depb,
    const float* __restrict__ revb1, const float* __restrict__ revW2,
    const float* __restrict__ revb2,
    const float* __restrict__ revg,  const float* __restrict__ revb,
    const float* __restrict__ projW, const float* __restrict__ projb,
    float* __restrict__ out, int n) {
    extern __shared__ float sm[];
    float* W  = sm;            // [128][72]
    float* Xs = sm + 9216;     // [128][68]
    float* Dp = sm + 17920;
    float* Rv = sm + 26624;
    float* V  = sm + 35328;    // 576
    float* CP = sm + 35904;    // 512
    float* DG = sm + 36416;    // 256

    int tid = threadIdx.x;
    int row0 = blockIdx.x * 128;
    int lane = tid & 31, wid = tid >> 5;
    int gid = lane >> 2, tig = lane & 3;
    int m0 = wid * 16;
    const unsigned FULL = 0xffffffffu;

    if (tid < 64) {
        V[tid]       = depb2[tid];
        V[64 + tid]  = revb2[tid];
        V[128 + tid] = depg[tid];
        V[192 + tid] = depb[tid];
        V[256 + tid] = revg[tid];
        V[320 + tid] = revb[tid];
        V[384 + tid] = projb[tid];
        V[448 + tid] = depb1[tid];
        V[512 + tid] = revb1[tid];
    }
    if (tid < 128) {
        int row = row0 + tid;
        DG[tid]       = (row < n) ? (float)(g_ptrD[row + 1] - g_ptrD[row]) : 0.f;
        DG[128 + tid] = (row < n) ? (float)(g_ptrR[row + 1] - g_ptrR[row]) : 0.f;
    }
    __syncthreads();   // V must be visible to all warps before agg

    // ============ stage 1: dep agg -> Xs, then GEMM + bias ============
    for (int i = tid; i < 4096; i += 256) W[(i >> 6) * 72 + (i & 63)] = depW2[i];
#pragma unroll 1
    for (int t = 0; t < 16; t++) {
        int rr = wid * 16 + t;
        int r = row0 + rr;
        float s0 = 0.f, s1 = 0.f;
        if (r < n) {
            int a0 = g_ptrD[r], a1 = g_ptrD[r + 1];
            float2 cv = *reinterpret_cast<const float2*>(&g_Cdep[r * 64 + 2 * lane]);
            float c0 = cv.x + V[448 + 2 * lane];
            float c1 = cv.y + V[448 + 2 * lane + 1];
            for (int i0 = a0; i0 < a1; i0 += 32) {
                int cnt = min(32, a1 - i0);
                int mi = (lane < cnt) ? g_srcD[i0 + lane] : 0;
                for (int j = 0; j < cnt; j++) {
                    int xs = __shfl_sync(FULL, mi, j);
                    float2 b = *reinterpret_cast<const float2*>(&g_Bdep[xs * 64 + 2 * lane]);
                    s0 += leaky(c0 + b.x);
                    s1 += leaky(c1 + b.y);
                }
            }
        }
        Xs[rr * TS + 2 * lane]     = s0;
        Xs[rr * TS + 2 * lane + 1] = s1;
    }
    __syncthreads();

    {
        float4 acc[8];
#pragma unroll
        for (int nt = 0; nt < 8; nt++) acc[nt] = make_float4(0.f, 0.f, 0.f, 0.f);
#pragma unroll
        for (int ks = 0; ks < 8; ks++) {
            int kb = ks * 8;
            uint32 ah[4], al[4];
            split_tf32(Xs[(m0 + gid) * TS + kb + tig],     ah[0], al[0]);
            split_tf32(Xs[(m0 + gid + 8) * TS + kb + tig], ah[1], al[1]);
            split_tf32(Xs[(m0 + gid) * TS + kb + tig + 4],     ah[2], al[2]);
            split_tf32(Xs[(m0 + gid + 8) * TS + kb + tig + 4], ah[3], al[3]);
#pragma unroll
            for (int nt = 0; nt < 8; nt++) {
                int nc = nt * 8 + gid;
                uint32 bh0, bl0, bh1, bl1;
                split_tf32(W[(kb + tig) * 72 + nc],     bh0, bl0);
                split_tf32(W[(kb + tig + 4) * 72 + nc], bh1, bl1);
                mma_tf32(acc[nt], ah[0], ah[1], ah[2], ah[3], bh0, bh1);
                mma_tf32(acc[nt], ah[0], ah[1], ah[2], ah[3], bl0, bl1);
                mma_tf32(acc[nt], al[0], al[1], al[2], al[3], bh0, bh1);
            }
        }
        float dgA = DG[m0 + gid], dgB = DG[m0 + gid + 8];
#pragma unroll
        for (int nt = 0; nt < 8; nt++) {
            int c = nt * 8 + tig * 2;
            Dp[(m0 + gid) * TS + c]     = acc[nt].x + dgA * V[c];
            Dp[(m0 + gid) * TS + c + 1] = acc[nt].y + dgA * V[c + 1];
            Dp[(m0 + gid + 8) * TS + c]     = acc[nt].z + dgB * V[c];
            Dp[(m0 + gid + 8) * TS + c + 1] = acc[nt].w + dgB * V[c + 1];
        }
    }
    __syncthreads();

    // LN dep; concurrently stage W2r + agg rev into Xs
#pragma unroll
    for (int t = 0; t < 16; t++) {
        int row = wid * 16 + t;
        float h0 = Dp[row * TS + lane];
        float h1 = Dp[row * TS + 32 + lane];
        float m = warp_sum(h0 + h1) * (1.f / 64.f);
        float e0 = h0 - m, e1 = h1 - m;
        float v = warp_sum(e0 * e0 + e1 * e1) * (1.f / 64.f);
        float inv = rsqrtf(v + 1e-5f);
        Dp[row * TS + lane]      = leaky(e0 * inv * V[128 + lane] + V[192 + lane]);
        Dp[row * TS + 32 + lane] = leaky(e1 * inv * V[160 + lane] + V[224 + lane]);
    }
    for (int i = tid; i < 4096; i += 256) W[(i >> 6) * 72 + (i & 63)] = revW2[i];
#pragma unroll 1
    for (int t = 0; t < 16; t++) {
        int rr = wid * 16 + t;
        int r = row0 + rr;
        float s0 = 0.f, s1 = 0.f;
        if (r < n) {
            int a0 = g_ptrR[r], a1 = g_ptrR[r + 1];
            float2 cv = *reinterpret_cast<const float2*>(&g_Crev[r * 64 + 2 * lane]);
            float c0 = cv.x + V[512 + 2 * lane];
            float c1 = cv.y + V[512 + 2 * lane + 1];
            for (int i0 = a0; i0 < a1; i0 += 32) {
                int cnt = min(32, a1 - i0);
                int mi = (lane < cnt) ? g_srcR[i0 + lane] : 0;
                for (int j = 0; j < cnt; j++) {
                    int xs = __shfl_sync(FULL, mi, j);
                    float2 b = *reinterpret_cast<const float2*>(&g_Brev[xs * 64 + 2 * lane]);
                    s0 += leaky(c0 + b.x);
                    s1 += leaky(c1 + b.y);
                }
            }
        }
        Xs[rr * TS + 2 * lane]     = s0;
        Xs[rr * TS + 2 * lane + 1] = s1;
    }
    __syncthreads();

    // ============ stage 2: rev ============
    {
        float4 acc[8];
#pragma unroll
        for (int nt = 0; nt < 8; nt++) acc[nt] = make_float4(0.f, 0.f, 0.f, 0.f);
#pragma unroll
        for (int ks = 0; ks < 8; ks++) {
            int kb = ks * 8;
            uint32 ah[4], al[4];
            split_tf32(Xs[(m0 + gid) * TS + kb + tig],     ah[0], al[0]);
            split_tf32(Xs[(m0 + gid + 8) * TS + kb + tig], ah[1], al[1]);
            split_tf32(Xs[(m0 + gid) * TS + kb + tig + 4],     ah[2], al[2]);
            split_tf32(Xs[(m0 + gid + 8) * TS + kb + tig + 4], ah[3], al[3]);
#pragma unroll
            for (int nt = 0; nt < 8; nt++) {
                int nc = nt * 8 + gid;
                uint32 bh0, bl0, bh1, bl1;
                split_tf32(W[(kb + tig) * 72 + nc],     bh0, bl0);
                split_tf32(W[(kb + tig + 4) * 72 + nc], bh1, bl1);
                mma_tf32(acc[nt], ah[0], ah[1], ah[2], ah[3], bh0, bh1);
                mma_tf32(acc[nt], ah[0], ah[1], ah[2], ah[3], bl0, bl1);
                mma_tf32(acc[nt], al[0], al[1], al[2], al[3], bh0, bh1);
            }
        }
        float dgA = DG[128 + m0 + gid], dgB = DG[128 + m0 + gid + 8];
#pragma unroll
        for (int nt = 0; nt < 8; nt++) {
            int c = nt * 8 + tig * 2;
            Rv[(m0 + gid) * TS + c]     = acc[nt].x + dgA * V[64 + c];
            Rv[(m0 + gid) * TS + c + 1] = acc[nt].y + dgA * V[64 + c + 1];
            Rv[(m0 + gid + 8) * TS + c]     = acc[nt].z + dgB * V[64 + c];
            Rv[(m0 + gid + 8) * TS + c + 1] = acc[nt].w + dgB * V[64 + c + 1];
        }
    }
    __syncthreads();

    // LN rev; concurrently stage P
#pragma unroll
    for (int t = 0; t < 16; t++) {
        int row = wid * 16 + t;
        float h0 = Rv[row * TS + lane];
        float h1 = Rv[row * TS + 32 + lane];
        float m = warp_sum(h0 + h1) * (1.f / 64.f);
        float e0 = h0 - m, e1 = h1 - m;
        float v = warp_sum(e0 * e0 + e1 * e1) * (1.f / 64.f);
        float inv = rsqrtf(v + 1e-5f);
        Rv[row * TS + lane]      = leaky(e0 * inv * V[256 + lane] + V[320 + lane]);
        Rv[row * TS + 32 + lane] = leaky(e1 * inv * V[288 + lane] + V[352 + lane]);
    }
    for (int i = tid; i < 8192; i += 256) W[(i >> 6) * 72 + (i & 63)] = projW[i];
    __syncthreads();

    // ============ stage 3: proj + reduce ============
    {
        float4 acc[8];
#pragma unroll
        for (int nt = 0; nt < 8; nt++) acc[nt] = make_float4(0.f, 0.f, 0.f, 0.f);
#pragma unroll
        for (int ks = 0; ks < 16; ks++) {
            const float* A = (ks < 8) ? Dp : Rv;
            int kb = (ks & 7) * 8;
            uint32 ah[4], al[4];
            split_tf32(A[(m0 + gid) * TS + kb + tig],     ah[0], al[0]);
            split_tf32(A[(m0 + gid + 8) * TS + kb + tig], ah[1], al[1]);
            split_tf32(A[(m0 + gid) * TS + kb + tig + 4],     ah[2], al[2]);
            split_tf32(A[(m0 + gid + 8) * TS + kb + tig + 4], ah[3], al[3]);
#pragma unroll
            for (int nt = 0; nt < 8; nt++) {
                int nc = nt * 8 + gid;
                uint32 bh0, bl0, bh1, bl1;
                split_tf32(W[(ks * 8 + tig) * 72 + nc],     bh0, bl0);
                split_tf32(W[(ks * 8 + tig + 4) * 72 + nc], bh1, bl1);
                mma_tf32(acc[nt], ah[0], ah[1], ah[2], ah[3], bh0, bh1);
                mma_tf32(acc[nt], ah[0], ah[1], ah[2], ah[3], bl0, bl1);
                mma_tf32(acc[nt], al[0], al[1], al[2], al[3], bh0, bh1);
            }
        }
        int rowA = row0 + m0 + gid;
        int rowB = rowA + 8;
#pragma unroll
        for (int nt = 0; nt < 8; nt++) {
            int c = nt * 8 + tig * 2;
            float t0 = leaky(acc[nt].x + V[384 + c]);
            float t1 = leaky(acc[nt].y + V[384 + c + 1]);
            float t2 = leaky(acc[nt].z + V[384 + c]);
            float t3 = leaky(acc[nt].w + V[384 + c + 1]);
            float sx = ((rowA < n) ? t0 : 0.f) + ((rowB < n) ? t2 : 0.f);
            float sy = ((rowA < n) ? t1 : 0.f) + ((rowB < n) ? t3 : 0.f);
            sx += __shfl_xor_sync(FULL, sx, 4);
            sy += __shfl_xor_sync(FULL, sy, 4);
            sx += __shfl_xor_sync(FULL, sx, 8);
            sy += __shfl_xor_sync(FULL, sy, 8);
            sx += __shfl_xor_sync(FULL, sx, 16);
            sy += __shfl_xor_sync(FULL, sy, 16);
            if (gid == 0) {
                CP[wid * 64 + c]     = sx;
                CP[wid * 64 + c + 1] = sy;
            }
            if (rowA == 0) {
                out[64 + c]     = t0;
                out[64 + c + 1] = t1;
            }
        }
    }
    __syncthreads();
    if (tid < 64) {
        float s = 0.f;
#pragma unroll
        for (int g = 0; g < 8; g++) s += CP[g * 64 + tid];
        atomicAdd(&g_colsum[tid], s);
    }
}

// ---------------------------------------------------------------------------
// K6: finalize
// ---------------------------------------------------------------------------
__global__ void k_final(const int* __restrict__ counts,
                        const float* __restrict__ devx,
                        const float* __restrict__ timex,
                        const float* __restrict__ devW,
                        const float* __restrict__ devb,
                        float* __restrict__ out) {
    int tid = threadIdx.x;
    if (tid < 64) {
        int c = counts[0];
        if (c < 1) c = 1;
        out[tid] = g_colsum[tid] / (float)c;
    } else if (tid < 128) {
        int j = tid - 64;
        float p = devb[j];
#pragma unroll 8
        for (int k = 0; k < 96; k++) p += devx[k] * devW[k * 64 + j];
        p += (timex[0] * 1e-5f) * devW[96 * 64 + j];
        out[128 + j] = leaky(p);
    }
}

// ---------------------------------------------------------------------------
// Launch
// ---------------------------------------------------------------------------
extern "C" void kernel_launch(void* const* d_in, const int* in_sizes, int n_in,
                              void* d_out, int out_size) {
    const float* data_x    = (const float*)d_in[0];
    const float* tasks_x   = (const float*)d_in[1];
    const float* devices_x = (const float*)d_in[2];
    const float* time_x    = (const float*)d_in[3];
    const int*   dt_src    = (const int*)d_in[4];
    const int*   dt_dst    = (const int*)d_in[5];
    const int*   tt_src    = (const int*)d_in[6];
    const int*   tt_dst    = (const int*)d_in[7];
    const int*   counts    = (const int*)d_in[8];
    const float* gcWrel    = (const float*)d_in[9];
    const float* gcbrel    = (const float*)d_in[10];
    const float* gcWroot   = (const float*)d_in[11];
    const float* gclng     = (const float*)d_in[12];
    const float* gclnb     = (const float*)d_in[13];
    const float* depW1     = (const float*)d_in[14];
    const float* depb1     = (const float*)d_in[15];
    const float* depW2     = (const float*)d_in[16];
    const float* depb2     = (const float*)d_in[17];
    const float* deplng    = (const float*)d_in[18];
    const float* deplnb    = (const float*)d_in[19];
    const float* revW1     = (const float*)d_in[20];
    const float* revb1     = (const float*)d_in[21];
    const float* revW2     = (const float*)d_in[22];
    const float* revb2     = (const float*)d_in[23];
    const float* revlng    = (const float*)d_in[24];
    const float* revlnb    = (const float*)d_in[25];
    const float* devW      = (const float*)d_in[26];
    const float* devb      = (const float*)d_in[27];
    const float* projW     = (const float*)d_in[28];
    const float* projb     = (const float*)d_in[29];
    float* out = (float*)d_out;

    int n    = in_sizes[1] / 12;
    int e_dt = in_sizes[4];
    int e_tt = in_sizes[6];
    int nblk = (n + 1023) / 1024;
    int emax = e_dt > e_tt ? e_dt : e_tt;

    cudaFuncSetAttribute(k_gemm_tc, cudaFuncAttributeMaxDynamicSharedMemorySize, 104448);
    cudaFuncSetAttribute(k_tail2,   cudaFuncAttributeMaxDynamicSharedMemorySize, 146688);

    k_zero<<<(n * 5 + 255) / 256, 256>>>(n);
    k_edges_pre<<<(emax + 255) / 256, 256>>>(data_x, dt_src, dt_dst, e_dt,
                                             tt_src, tt_dst, e_tt);

    dim3 sg(nblk, 2);
    k_scan_blk<<<sg, 256>>>(n);
    k_scan_top<<<1, 64>>>(nblk);
    k_scan_fix<<<sg, 256>>>(n, e_tt);
    k_scatter<<<(e_tt + 255) / 256, 256>>>(tt_src, tt_dst, e_tt);

    k_fused<<<(n * 32 + 255) / 256, 256>>>(tasks_x, gcWrel, gcbrel, gcWroot, gclng, gclnb, n);

    int gb = (n + 127) / 128;
    k_gemm_tc<<<gb, 256, 104448>>>(depW1, revW1, n);

    k_tail2<<<gb, 256, 146688>>>(depb1, depW2, depb2, deplng, deplnb,
                                 revb1, revW2, revb2, revlng, revlnb,
                                 projW, projb, out, n);
    k_final<<<1, 128>>>(counts, devices_x, time_x, devW, devb, out);
}

// round 12
// speedup vs baseline: 1.6656x; 1.6656x over previous
#include <cuda_runtime.h>

#define NT_MAX 200000
#define ETT_MAX 1100000

typedef unsigned int uint32;

// ---------------------------------------------------------------------------
// Scratch (__device__ globals — allocation-free rule)
// ---------------------------------------------------------------------------
__device__ float g_agg  [NT_MAX * 5];
__device__ float g_Bdep [NT_MAX * 64];
__device__ float g_Cdep [NT_MAX * 64];
__device__ float g_Brev [NT_MAX * 64];
__device__ float g_Crev [NT_MAX * 64];
__device__ float g_Sdep [NT_MAX * 64];
__device__ float g_Srev [NT_MAX * 64];
__device__ int   g_degD [NT_MAX];
__device__ int   g_degR [NT_MAX];
__device__ int   g_ptrD [NT_MAX + 1];
__device__ int   g_ptrR [NT_MAX + 1];
__device__ int   g_curD [NT_MAX];
__device__ int   g_curR [NT_MAX];
__device__ int   g_srcD [ETT_MAX];
__device__ int   g_srcR [ETT_MAX];
__device__ int   g_bsumD[512];
__device__ int   g_bsumR[512];
__device__ float g_colsum[64];

__device__ __forceinline__ float leaky(float x) { return x > 0.f ? x : 0.01f * x; }

__device__ __forceinline__ float warp_sum(float v) {
#pragma unroll
    for (int o = 16; o > 0; o >>= 1) v += __shfl_xor_sync(0xffffffffu, v, o);
    return v;
}

// ---- tf32 helpers ---------------------------------------------------------
__device__ __forceinline__ uint32 tf32_of(float x) {
    uint32 u;
    asm("cvt.rna.tf32.f32 %0, %1;" : "=r"(u) : "f"(x));
    return u;
}
__device__ __forceinline__ void split_tf32(float x, uint32& hi, uint32& lo) {
    hi = tf32_of(x);
    lo = tf32_of(x - __uint_as_float(hi));
}
__device__ __forceinline__ void mma_tf32(float4& d,
                                         uint32 a0, uint32 a1, uint32 a2, uint32 a3,
                                         uint32 b0, uint32 b1) {
    asm("mma.sync.aligned.m16n8k8.row.col.f32.tf32.tf32.f32 "
        "{%0,%1,%2,%3},{%4,%5,%6,%7},{%8,%9},{%0,%1,%2,%3};"
        : "+f"(d.x), "+f"(d.y), "+f"(d.z), "+f"(d.w)
        : "r"(a0), "r"(a1), "r"(a2), "r"(a3), "r"(b0), "r"(b1));
}

// ---------------------------------------------------------------------------
// K0: zero accumulators
// ---------------------------------------------------------------------------
__global__ void k_zero(int n) {
    int i = blockIdx.x * blockDim.x + threadIdx.x;
    if (i < n * 5) g_agg[i] = 0.f;
    if (i < n) { g_degD[i] = 0; g_degR[i] = 0; }
    if (i < 64) g_colsum[i] = 0.f;
}

// ---------------------------------------------------------------------------
// K1: data->task scatter-add + tt degree histograms (fused)
// ---------------------------------------------------------------------------
__global__ void k_edges_pre(const float* __restrict__ data_x,
                            const int* __restrict__ dsrc, const int* __restrict__ ddst,
                            int e_dt,
                            const int* __restrict__ tsrc, const int* __restrict__ tdst,
                            int e_tt) {
    int e = blockIdx.x * blockDim.x + threadIdx.x;
    if (e < e_dt) {
        int s = __ldg(&dsrc[e]);
        int d = __ldg(&ddst[e]);
        const float* xr = data_x + s * 5;
        float* ar = g_agg + d * 5;
#pragma unroll
        for (int k = 0; k < 5; k++) atomicAdd(ar + k, __ldg(&xr[k]));
    }
    if (e < e_tt) {
        atomicAdd(&g_degD[__ldg(&tdst[e])], 1);
        atomicAdd(&g_degR[__ldg(&tsrc[e])], 1);
    }
}

// ---------------------------------------------------------------------------
// Scan stage 1
// ---------------------------------------------------------------------------
__global__ __launch_bounds__(256) void k_scan_blk(int n) {
    int arr = blockIdx.y;
    const int* deg = arr ? g_degR : g_degD;
    int* ptr = arr ? g_ptrR : g_ptrD;
    int* bsum = arr ? g_bsumR : g_bsumD;
    __shared__ int sh[256];
    int tid = threadIdx.x;
    int base = blockIdx.x * 1024;
    int v[4]; int s = 0;
#pragma unroll
    for (int j = 0; j < 4; j++) {
        int idx = base + tid * 4 + j;
        v[j] = (idx < n) ? deg[idx] : 0;
        s += v[j];
    }
    sh[tid] = s;
    __syncthreads();
#pragma unroll
    for (int d = 1; d < 256; d <<= 1) {
        int t = 0;
        if (tid >= d) t = sh[tid - d];
        __syncthreads();
        sh[tid] += t;
        __syncthreads();
    }
    int off = sh[tid] - s;
#pragma unroll
    for (int j = 0; j < 4; j++) {
        int idx = base + tid * 4 + j;
        if (idx < n) ptr[idx] = off;
        off += v[j];
    }
    if (tid == 0) bsum[blockIdx.x] = sh[255];
}

// ---------------------------------------------------------------------------
// Scan stage 2: warp-parallel scan of block sums (one warp per array)
// ---------------------------------------------------------------------------
__global__ void k_scan_top(int nblk) {
    int lane = threadIdx.x & 31;
    int* bs = (threadIdx.x < 32) ? g_bsumD : g_bsumR;
    int base = 0;
    for (int i0 = 0; i0 < nblk; i0 += 32) {
        int idx = i0 + lane;
        int v = (idx < nblk) ? bs[idx] : 0;
        int incl = v;
#pragma unroll
        for (int o = 1; o < 32; o <<= 1) {
            int t = __shfl_up_sync(0xffffffffu, incl, o);
            if (lane >= o) incl += t;
        }
        if (idx < nblk) bs[idx] = base + incl - v;
        base += __shfl_sync(0xffffffffu, incl, 31);
    }
}

// ---------------------------------------------------------------------------
// Scan stage 3
// ---------------------------------------------------------------------------
__global__ __launch_bounds__(256) void k_scan_fix(int n, int E) {
    int arr = blockIdx.y;
    int* ptr = arr ? g_ptrR : g_ptrD;
    int* cur = arr ? g_curR : g_curD;
    const int* bsum = arr ? g_bsumR : g_bsumD;
    int off = bsum[blockIdx.x];
    int base = blockIdx.x * 1024 + threadIdx.x * 4;
#pragma unroll
    for (int j = 0; j < 4; j++) {
        int idx = base + j;
        if (idx < n) { int v = ptr[idx] + off; ptr[idx] = v; cur[idx] = v; }
    }
    if (blockIdx.x == 0 && threadIdx.x == 0) ptr[n] = E;
}

// ---------------------------------------------------------------------------
// K1c: scatter edges into CSR
// ---------------------------------------------------------------------------
__global__ void k_scatter(const int* __restrict__ tsrc, const int* __restrict__ tdst, int E) {
    int e = blockIdx.x * blockDim.x + threadIdx.x;
    if (e >= E) return;
    int s = __ldg(&tsrc[e]);
    int d = __ldg(&tdst[e]);
    int p = atomicAdd(&g_curD[d], 1);
    g_srcD[p] = s;
    int q = atomicAdd(&g_curR[s], 1);
    g_srcR[q] = d;
}

// ---------------------------------------------------------------------------
// K3: fused-LN + tensor-core B/C GEMMs (3xTF32, on-the-fly split).
// Block = 128 rows, 256 threads, 2 blocks/SM (104448 B smem).
// Prologue: warp computes LN(fused) for 16 rows directly into Xs (verified in R5).
// Mainloop/store identical to the proven 824us k_gemm_tc.
// ---------------------------------------------------------------------------
__global__ __launch_bounds__(256, 2) void k_gemm_tc(
    const float* __restrict__ tasks_x,
    const float* __restrict__ Wrel, const float* __restrict__ brel,
    const float* __restrict__ Wroot,
    const float* __restrict__ lng, const float* __restrict__ lnb,
    const float* __restrict__ depW1, const float* __restrict__ revW1, int n) {
    extern __shared__ float sm[];
    float* Xs  = sm;            // [128][68]
    float* WsD = sm + 8704;     // [64][136]
    float* WsR = sm + 17408;    // [64][136]
    int tid = threadIdx.x;
    int lane = tid & 31, wid = tid >> 5;
    int row0 = blockIdx.x * 128;

    // W staging (both convs): [W1b | W1a-W1b]
    for (int idx = tid; idx < 8192; idx += 256) {
        int k = idx >> 7, j = idx & 127;
        float wBd = depW1[(64 + k) * 64 + (j & 63)];
        WsD[k * 136 + j] = (j < 64) ? wBd : (depW1[k * 64 + (j - 64)] - wBd);
        float wBr = revW1[(64 + k) * 64 + (j & 63)];
        WsR[k * 136 + j] = (j < 64) ? wBr : (revW1[k * 64 + (j - 64)] - wBr);
    }

    // fused-LN -> Xs (warp per row, 16 rows/warp)
#pragma unroll 1
    for (int t = 0; t < 16; t++) {
        int rr = wid * 16 + t;
        int r = row0 + rr;
        float y0 = 0.f, y1 = 0.f;
        if (r < n) {
            float p0 = __ldg(&brel[lane]);
            float p1 = __ldg(&brel[lane + 32]);
            const float* ar = g_agg + r * 5;
#pragma unroll
            for (int k = 0; k < 5; k++) {
                float a = ar[k];
                p0 += a * __ldg(&Wrel[k * 64 + lane]);
                p1 += a * __ldg(&Wrel[k * 64 + lane + 32]);
            }
            const float* tr = tasks_x + r * 12;
#pragma unroll
            for (int k = 0; k < 12; k++) {
                float tv = __ldg(&tr[k]);
                p0 += tv * __ldg(&Wroot[k * 64 + lane]);
                p1 += tv * __ldg(&Wroot[k * 64 + lane + 32]);
            }
            float m = warp_sum(p0 + p1) * (1.f / 64.f);
            float d0 = p0 - m, d1 = p1 - m;
            float v = warp_sum(d0 * d0 + d1 * d1) * (1.f / 64.f);
            float inv = rsqrtf(v + 1e-5f);
            y0 = leaky(d0 * inv * __ldg(&lng[lane])      + __ldg(&lnb[lane]));
            y1 = leaky(d1 * inv * __ldg(&lng[lane + 32]) + __ldg(&lnb[lane + 32]));
        }
        Xs[rr * 68 + lane]      = y0;
        Xs[rr * 68 + 32 + lane] = y1;
    }
    __syncthreads();

    int gid = lane >> 2, tig = lane & 3;
    int m0 = (wid & 3) * 32;
    int nhalf = (wid >> 2) * 64;

#pragma unroll 1
    for (int conv = 0; conv < 2; conv++) {
        const float* Ws = conv ? WsR : WsD;
        float4 acc[2][8];
#pragma unroll
        for (int mt = 0; mt < 2; mt++)
#pragma unroll
            for (int nt = 0; nt < 8; nt++) acc[mt][nt] = make_float4(0.f, 0.f, 0.f, 0.f);

#pragma unroll
        for (int ks = 0; ks < 8; ks++) {
            int kb = ks * 8;
            uint32 ah[2][4], al[2][4];
#pragma unroll
            for (int mt = 0; mt < 2; mt++) {
                int rb = m0 + mt * 16;
                split_tf32(Xs[(rb + gid) * 68 + kb + tig],     ah[mt][0], al[mt][0]);
                split_tf32(Xs[(rb + gid + 8) * 68 + kb + tig], ah[mt][1], al[mt][1]);
                split_tf32(Xs[(rb + gid) * 68 + kb + tig + 4],     ah[mt][2], al[mt][2]);
                split_tf32(Xs[(rb + gid + 8) * 68 + kb + tig + 4], ah[mt][3], al[mt][3]);
            }
#pragma unroll
            for (int nt = 0; nt < 8; nt++) {
                int nc = nhalf + nt * 8 + gid;
                uint32 bh0, bl0, bh1, bl1;
                split_tf32(Ws[(kb + tig) * 136 + nc],     bh0, bl0);
                split_tf32(Ws[(kb + tig + 4) * 136 + nc], bh1, bl1);
#pragma unroll
                for (int mt = 0; mt < 2; mt++) {
                    mma_tf32(acc[mt][nt], ah[mt][0], ah[mt][1], ah[mt][2], ah[mt][3], bh0, bh1);
                    mma_tf32(acc[mt][nt], ah[mt][0], ah[mt][1], ah[mt][2], ah[mt][3], bl0, bl1);
                    mma_tf32(acc[mt][nt], al[mt][0], al[mt][1], al[mt][2], al[mt][3], bh0, bh1);
                }
            }
        }

        float* O = (nhalf == 0) ? (conv ? g_Brev : g_Bdep) : (conv ? g_Crev : g_Cdep);
#pragma unroll
        for (int mt = 0; mt < 2; mt++) {
#pragma unroll
            for (int nt = 0; nt < 8; nt++) {
                int c = nt * 8 + tig * 2;
                int rowA = row0 + m0 + mt * 16 + gid;
                int rowB = rowA + 8;
                if (rowA < n)
                    *reinterpret_cast<float2*>(&O[rowA * 64 + c]) =
                        make_float2(acc[mt][nt].x, acc[mt][nt].y);
                if (rowB < n)
                    *reinterpret_cast<float2*>(&O[rowB * 64 + c]) =
                        make_float2(acc[mt][nt].z, acc[mt][nt].w);
            }
        }
    }
}

// ---------------------------------------------------------------------------
// K4: edge aggregation (R6-proven). Warp per node, lane owns channels (2l,2l+1).
// Launched SEPARATELY per conv to keep each 102MB gather working set L2-resident.
// ---------------------------------------------------------------------------
__global__ __launch_bounds__(256) void k_agg(const float* __restrict__ b1,
                                             int n, int conv) {
    const int* ptr  = conv ? g_ptrR : g_ptrD;
    const int* srcA = conv ? g_srcR : g_srcD;
    const float* B  = conv ? g_Brev : g_Bdep;
    const float* C  = conv ? g_Crev : g_Cdep;
    float* S        = conv ? g_Srev : g_Sdep;
    const unsigned FULL = 0xffffffffu;
    int lane = threadIdx.x & 31, wid = threadIdx.x >> 5;
    int r = blockIdx.x * 8 + wid;
    if (r >= n) return;
    int a0 = ptr[r], a1 = ptr[r + 1];
    float2 cv = *reinterpret_cast<const float2*>(&C[r * 64 + 2 * lane]);
    float c0 = cv.x + __ldg(&b1[2 * lane]);
    float c1 = cv.y + __ldg(&b1[2 * lane + 1]);
    float s0 = 0.f, s1 = 0.f;
    for (int i0 = a0; i0 < a1; i0 += 32) {
        int cnt = min(32, a1 - i0);
        int mi = (lane < cnt) ? srcA[i0 + lane] : 0;
        int j = 0;
        for (; j + 4 <= cnt; j += 4) {
            int x0 = __shfl_sync(FULL, mi, j);
            int x1 = __shfl_sync(FULL, mi, j + 1);
            int x2 = __shfl_sync(FULL, mi, j + 2);
            int x3 = __shfl_sync(FULL, mi, j + 3);
            float2 b0 = *reinterpret_cast<const float2*>(&B[x0 * 64 + 2 * lane]);
            float2 b1v = *reinterpret_cast<const float2*>(&B[x1 * 64 + 2 * lane]);
            float2 b2 = *reinterpret_cast<const float2*>(&B[x2 * 64 + 2 * lane]);
            float2 b3 = *reinterpret_cast<const float2*>(&B[x3 * 64 + 2 * lane]);
            s0 += leaky(c0 + b0.x) + leaky(c0 + b1v.x) + leaky(c0 + b2.x) + leaky(c0 + b3.x);
            s1 += leaky(c1 + b0.y) + leaky(c1 + b1v.y) + leaky(c1 + b2.y) + leaky(c1 + b3.y);
        }
        for (; j < cnt; j++) {
            int xs = __shfl_sync(FULL, mi, j);
            float2 b = *reinterpret_cast<const float2*>(&B[xs * 64 + 2 * lane]);
            s0 += leaky(c0 + b.x);
            s1 += leaky(c1 + b.y);
        }
    }
    *reinterpret_cast<float2*>(&S[r * 64 + 2 * lane]) = make_float2(s0, s1);
}

// ---------------------------------------------------------------------------
// K5: tiled tail, TC GEMMs (3xTF32 on-the-fly split) — exact 824us version.
// Block = 128 rows, 256 threads. Warp: 16 rows x 64 cols.
// smem floats: W [128][72] | Xs [128][68] | Dp | Rv | V 448 | CP 512 | DG 256
// ---------------------------------------------------------------------------
#define TS 68

__global__ __launch_bounds__(256) void k_tail2(
    const float* __restrict__ depW2, const float* __restrict__ depb2,
    const float* __restrict__ depg,  const float* __restrict__ depb,
    const float* __restrict__ revW2, const float* __restrict__ revb2,
    const float* __restrict__ revg,  const float* __restrict__ revb,
    const float* __restrict__ projW, const float* __restrict__ projb,
    float* __restrict__ out, int n) {
    extern __shared__ float sm[];
    float* W  = sm;            // [128][72]
    float* Xs = sm + 9216;     // [128][68]
    float* Dp = sm + 17920;
    float* Rv = sm + 26624;
    float* V  = sm + 35328;    // 448
    float* CP = sm + 35776;    // 512
    float* DG = sm + 36288;    // 256

    int tid = threadIdx.x;
    int row0 = blockIdx.x * 128;
    int lane = tid & 31, wid = tid >> 5;
    int gid = lane >> 2, tig = lane & 3;
    int m0 = wid * 16;
    const unsigned FULL = 0xffffffffu;

    if (tid < 64) {
        V[tid]       = depb2[tid];
        V[64 + tid]  = revb2[tid];
        V[128 + tid] = depg[tid];
        V[192 + tid] = depb[tid];
        V[256 + tid] = revg[tid];
        V[320 + tid] = revb[tid];
        V[384 + tid] = projb[tid];
    }
    if (tid < 128) {
        int row = row0 + tid;
        DG[tid]       = (row < n) ? (float)(g_ptrD[row + 1] - g_ptrD[row]) : 0.f;
        DG[128 + tid] = (row < n) ? (float)(g_ptrR[row + 1] - g_ptrR[row]) : 0.f;
    }

    // ============ stage 1: dep ============
    for (int i = tid; i < 4096; i += 256) W[(i >> 6) * 72 + (i & 63)] = depW2[i];
#pragma unroll
    for (int it = 0; it < 8; it++) {
        int fi = tid + it * 256;
        int r = fi >> 4, c4 = (fi & 15) * 4;
        float4 v = make_float4(0.f, 0.f, 0.f, 0.f);
        int row = row0 + r;
        if (row < n) v = *reinterpret_cast<const float4*>(&g_Sdep[row * 64 + c4]);
        *reinterpret_cast<float4*>(&Xs[r * TS + c4]) = v;
    }
    __syncthreads();

    {
        float4 acc[8];
#pragma unroll
        for (int nt = 0; nt < 8; nt++) acc[nt] = make_float4(0.f, 0.f, 0.f, 0.f);
#pragma unroll
        for (int ks = 0; ks < 8; ks++) {
            int kb = ks * 8;
            uint32 ah[4], al[4];
            split_tf32(Xs[(m0 + gid) * TS + kb + tig],     ah[0], al[0]);
            split_tf32(Xs[(m0 + gid + 8) * TS + kb + tig], ah[1], al[1]);
            split_tf32(Xs[(m0 + gid) * TS + kb + tig + 4],     ah[2], al[2]);
            split_tf32(Xs[(m0 + gid + 8) * TS + kb + tig + 4], ah[3], al[3]);
#pragma unroll
            for (int nt = 0; nt < 8; nt++) {
                int nc = nt * 8 + gid;
                uint32 bh0, bl0, bh1, bl1;
                split_tf32(W[(kb + tig) * 72 + nc],     bh0, bl0);
                split_tf32(W[(kb + tig + 4) * 72 + nc], bh1, bl1);
                mma_tf32(acc[nt], ah[0], ah[1], ah[2], ah[3], bh0, bh1);
                mma_tf32(acc[nt], ah[0], ah[1], ah[2], ah[3], bl0, bl1);
                mma_tf32(acc[nt], al[0], al[1], al[2], al[3], bh0, bh1);
            }
        }
        float dgA = DG[m0 + gid], dgB = DG[m0 + gid + 8];
#pragma unroll
        for (int nt = 0; nt < 8; nt++) {
            int c = nt * 8 + tig * 2;
            Dp[(m0 + gid) * TS + c]     = acc[nt].x + dgA * V[c];
            Dp[(m0 + gid) * TS + c + 1] = acc[nt].y + dgA * V[c + 1];
            Dp[(m0 + gid + 8) * TS + c]     = acc[nt].z + dgB * V[c];
            Dp[(m0 + gid + 8) * TS + c + 1] = acc[nt].w + dgB * V[c + 1];
        }
    }
    __syncthreads();

    // LN dep; concurrently stage W2r + load S_rev
#pragma unroll
    for (int t = 0; t < 16; t++) {
        int row = wid * 16 + t;
        float h0 = Dp[row * TS + lane];
        float h1 = Dp[row * TS + 32 + lane];
        float m = warp_sum(h0 + h1) * (1.f / 64.f);
        float e0 = h0 - m, e1 = h1 - m;
        float v = warp_sum(e0 * e0 + e1 * e1) * (1.f / 64.f);
        float inv = rsqrtf(v + 1e-5f);
        Dp[row * TS + lane]      = leaky(e0 * inv * V[128 + lane] + V[192 + lane]);
        Dp[row * TS + 32 + lane] = leaky(e1 * inv * V[160 + lane] + V[224 + lane]);
    }
    for (int i = tid; i < 4096; i += 256) W[(i >> 6) * 72 + (i & 63)] = revW2[i];
#pragma unroll
    for (int it = 0; it < 8; it++) {
        int fi = tid + it * 256;
        int r = fi >> 4, c4 = (fi & 15) * 4;
        float4 v = make_float4(0.f, 0.f, 0.f, 0.f);
        int row = row0 + r;
        if (row < n) v = *reinterpret_cast<const float4*>(&g_Srev[row * 64 + c4]);
        *reinterpret_cast<float4*>(&Xs[r * TS + c4]) = v;
    }
    __syncthreads();

    // ============ stage 2: rev ============
    {
        float4 acc[8];
#pragma unroll
        for (int nt = 0; nt < 8; nt++) acc[nt] = make_float4(0.f, 0.f, 0.f, 0.f);
#pragma unroll
        for (int ks = 0; ks < 8; ks++) {
            int kb = ks * 8;
            uint32 ah[4], al[4];
            split_tf32(Xs[(m0 + gid) * TS + kb + tig],     ah[0], al[0]);
            split_tf32(Xs[(m0 + gid + 8) * TS + kb + tig], ah[1], al[1]);
            split_tf32(Xs[(m0 + gid) * TS + kb + tig + 4],     ah[2], al[2]);
            split_tf32(Xs[(m0 + gid + 8) * TS + kb + tig + 4], ah[3], al[3]);
#pragma unroll
            for (int nt = 0; nt < 8; nt++) {
                int nc = nt * 8 + gid;
                uint32 bh0, bl0, bh1, bl1;
                split_tf32(W[(kb + tig) * 72 + nc],     bh0, bl0);
                split_tf32(W[(kb + tig + 4) * 72 + nc], bh1, bl1);
                mma_tf32(acc[nt], ah[0], ah[1], ah[2], ah[3], bh0, bh1);
                mma_tf32(acc[nt], ah[0], ah[1], ah[2], ah[3], bl0, bl1);
                mma_tf32(acc[nt], al[0], al[1], al[2], al[3], bh0, bh1);
            }
        }
        float dgA = DG[128 + m0 + gid], dgB = DG[128 + m0 + gid + 8];
#pragma unroll
        for (int nt = 0; nt < 8; nt++) {
            int c = nt * 8 + tig * 2;
            Rv[(m0 + gid) * TS + c]     = acc[nt].x + dgA * V[64 + c];
            Rv[(m0 + gid) * TS + c + 1] = acc[nt].y + dgA * V[64 + c + 1];
            Rv[(m0 + gid + 8) * TS + c]     = acc[nt].z + dgB * V[64 + c];
            Rv[(m0 + gid + 8) * TS + c + 1] = acc[nt].w + dgB * V[64 + c + 1];
        }
    }
    __syncthreads();

    // LN rev; concurrently stage P
#pragma unroll
    for (int t = 0; t < 16; t++) {
        int row = wid * 16 + t;
        float h0 = Rv[row * TS + lane];
        float h1 = Rv[row * TS + 32 + lane];
        float m = warp_sum(h0 + h1) * (1.f / 64.f);
        float e0 = h0 - m, e1 = h1 - m;
        float v = warp_sum(e0 * e0 + e1 * e1) * (1.f / 64.f);
        float inv = rsqrtf(v + 1e-5f);
        Rv[row * TS + lane]      = leaky(e0 * inv * V[256 + lane] + V[320 + lane]);
        Rv[row * TS + 32 + lane] = leaky(e1 * inv * V[288 + lane] + V[352 + lane]);
    }
    for (int i = tid; i < 8192; i += 256) W[(i >> 6) * 72 + (i & 63)] = projW[i];
    __syncthreads();

    // ============ stage 3: proj + reduce ============
    {
        float4 acc[8];
#pragma unroll
        for (int nt = 0; nt < 8; nt++) acc[nt] = make_float4(0.f, 0.f, 0.f, 0.f);
#pragma unroll
        for (int ks = 0; ks < 16; ks++) {
            const float* A = (ks < 8) ? Dp : Rv;
            int kb = (ks & 7) * 8;
            uint32 ah[4], al[4];
            split_tf32(A[(m0 + gid) * TS + kb + tig],     ah[0], al[0]);
            split_tf32(A[(m0 + gid + 8) * TS + kb + tig], ah[1], al[1]);
            split_tf32(A[(m0 + gid) * TS + kb + tig + 4],     ah[2], al[2]);
            split_tf32(A[(m0 + gid + 8) * TS + kb + tig + 4], ah[3], al[3]);
#pragma unroll
            for (int nt = 0; nt < 8; nt++) {
                int nc = nt * 8 + gid;
                uint32 bh0, bl0, bh1, bl1;
                split_tf32(W[(ks * 8 + tig) * 72 + nc],     bh0, bl0);
                split_tf32(W[(ks * 8 + tig + 4) * 72 + nc], bh1, bl1);
                mma_tf32(acc[nt], ah[0], ah[1], ah[2], ah[3], bh0, bh1);
                mma_tf32(acc[nt], ah[0], ah[1], ah[2], ah[3], bl0, bl1);
                mma_tf32(acc[nt], al[0], al[1], al[2], al[3], bh0, bh1);
            }
        }
        int rowA = row0 + m0 + gid;
        int rowB = rowA + 8;
#pragma unroll
        for (int nt = 0; nt < 8; nt++) {
            int c = nt * 8 + tig * 2;
            float t0 = leaky(acc[nt].x + V[384 + c]);
            float t1 = leaky(acc[nt].y + V[384 + c + 1]);
            float t2 = leaky(acc[nt].z + V[384 + c]);
            float t3 = leaky(acc[nt].w + V[384 + c + 1]);
            float sx = ((rowA < n) ? t0 : 0.f) + ((rowB < n) ? t2 : 0.f);
            float sy = ((rowA < n) ? t1 : 0.f) + ((rowB < n) ? t3 : 0.f);
            sx += __shfl_xor_sync(FULL, sx, 4);
            sy += __shfl_xor_sync(FULL, sy, 4);
            sx += __shfl_xor_sync(FULL, sx, 8);
            sy += __shfl_xor_sync(FULL, sy, 8);
            sx += __shfl_xor_sync(FULL, sx, 16);
            sy += __shfl_xor_sync(FULL, sy, 16);
            if (gid == 0) {
                CP[wid * 64 + c]     = sx;
                CP[wid * 64 + c + 1] = sy;
            }
            if (rowA == 0) {
                out[64 + c]     = t0;
                out[64 + c + 1] = t1;
            }
        }
    }
    __syncthreads();
    if (tid < 64) {
        float s = 0.f;
#pragma unroll
        for (int g = 0; g < 8; g++) s += CP[g * 64 + tid];
        atomicAdd(&g_colsum[tid], s);
    }
}

// ---------------------------------------------------------------------------
// K6: finalize
// ---------------------------------------------------------------------------
__global__ void k_final(const int* __restrict__ counts,
                        const float* __restrict__ devx,
                        const float* __restrict__ timex,
                        const float* __restrict__ devW,
                        const float* __restrict__ devb,
                        float* __restrict__ out) {
    int tid = threadIdx.x;
    if (tid < 64) {
        int c = counts[0];
        if (c < 1) c = 1;
        out[tid] = g_colsum[tid] / (float)c;
    } else if (tid < 128) {
        int j = tid - 64;
        float p = devb[j];
#pragma unroll 8
        for (int k = 0; k < 96; k++) p += devx[k] * devW[k * 64 + j];
        p += (timex[0] * 1e-5f) * devW[96 * 64 + j];
        out[128 + j] = leaky(p);
    }
}

// ---------------------------------------------------------------------------
// Launch
// ---------------------------------------------------------------------------
extern "C" void kernel_launch(void* const* d_in, const int* in_sizes, int n_in,
                              void* d_out, int out_size) {
    const float* data_x    = (const float*)d_in[0];
    const float* tasks_x   = (const float*)d_in[1];
    const float* devices_x = (const float*)d_in[2];
    const float* time_x    = (const float*)d_in[3];
    const int*   dt_src    = (const int*)d_in[4];
    const int*   dt_dst    = (const int*)d_in[5];
    const int*   tt_src    = (const int*)d_in[6];
    const int*   tt_dst    = (const int*)d_in[7];
    const int*   counts    = (const int*)d_in[8];
    const float* gcWrel    = (const float*)d_in[9];
    const float* gcbrel    = (const float*)d_in[10];
    const float* gcWroot   = (const float*)d_in[11];
    const float* gclng     = (const float*)d_in[12];
    const float* gclnb     = (const float*)d_in[13];
    const float* depW1     = (const float*)d_in[14];
    const float* depb1     = (const float*)d_in[15];
    const float* depW2     = (const float*)d_in[16];
    const float* depb2     = (const float*)d_in[17];
    const float* deplng    = (const float*)d_in[18];
    const float* deplnb    = (const float*)d_in[19];
    const float* revW1     = (const float*)d_in[20];
    const float* revb1     = (const float*)d_in[21];
    const float* revW2     = (const float*)d_in[22];
    const float* revb2     = (const float*)d_in[23];
    const float* revlng    = (const float*)d_in[24];
    const float* revlnb    = (const float*)d_in[25];
    const float* devW      = (const float*)d_in[26];
    const float* devb      = (const float*)d_in[27];
    const float* projW     = (const float*)d_in[28];
    const float* projb     = (const float*)d_in[29];
    float* out = (float*)d_out;

    int n    = in_sizes[1] / 12;
    int e_dt = in_sizes[4];
    int e_tt = in_sizes[6];
    int nblk = (n + 1023) / 1024;
    int emax = e_dt > e_tt ? e_dt : e_tt;

    cudaFuncSetAttribute(k_gemm_tc, cudaFuncAttributeMaxDynamicSharedMemorySize, 104448);
    cudaFuncSetAttribute(k_tail2,   cudaFuncAttributeMaxDynamicSharedMemorySize, 146176);

    k_zero<<<(n * 5 + 255) / 256, 256>>>(n);
    k_edges_pre<<<(emax + 255) / 256, 256>>>(data_x, dt_src, dt_dst, e_dt,
                                             tt_src, tt_dst, e_tt);

    dim3 sg(nblk, 2);
    k_scan_blk<<<sg, 256>>>(n);
    k_scan_top<<<1, 64>>>(nblk);
    k_scan_fix<<<sg, 256>>>(n, e_tt);
    k_scatter<<<(e_tt + 255) / 256, 256>>>(tt_src, tt_dst, e_tt);

    int gb = (n + 127) / 128;
    k_gemm_tc<<<gb, 256, 104448>>>(tasks_x, gcWrel, gcbrel, gcWroot, gclng, gclnb,
                                   depW1, revW1, n);

    int ab = (n + 7) / 8;
    k_agg<<<ab, 256>>>(depb1, n, 0);
    k_agg<<<ab, 256>>>(revb1, n, 1);

    k_tail2<<<gb, 256, 146176>>>(depW2, depb2, deplng, deplnb,
                                 revW2, revb2, revlng, revlnb,
                                 projW, projb, out, n);
    k_final<<<1, 128>>>(counts, devices_x, time_x, devW, devb, out);
}

// round 13
// speedup vs baseline: 1.7768x; 1.0668x over previous
#include <cuda_runtime.h>

#define NT_MAX 200000
#define ETT_MAX 1100000

typedef unsigned int uint32;

// ---------------------------------------------------------------------------
// Scratch (__device__ globals — allocation-free rule)
// ---------------------------------------------------------------------------
__device__ float g_agg  [NT_MAX * 8];   // padded row stride 8 for v4 red atomics
__device__ float g_fused[NT_MAX * 64];
__device__ float g_Bdep [NT_MAX * 64];
__device__ float g_Cdep [NT_MAX * 64];
__device__ float g_Brev [NT_MAX * 64];
__device__ float g_Crev [NT_MAX * 64];
__device__ float g_Sdep [NT_MAX * 64];
__device__ float g_Srev [NT_MAX * 64];
__device__ int   g_degD [NT_MAX];
__device__ int   g_degR [NT_MAX];
__device__ int   g_ptrD [NT_MAX + 1];
__device__ int   g_ptrR [NT_MAX + 1];
__device__ int   g_curD [NT_MAX];
__device__ int   g_curR [NT_MAX];
__device__ int   g_srcD [ETT_MAX];
__device__ int   g_srcR [ETT_MAX];
__device__ int   g_bsumD[512];
__device__ int   g_bsumR[512];
__device__ float g_colsum[64];

__device__ __forceinline__ float leaky(float x) { return x > 0.f ? x : 0.01f * x; }

__device__ __forceinline__ float warp_sum(float v) {
#pragma unroll
    for (int o = 16; o > 0; o >>= 1) v += __shfl_xor_sync(0xffffffffu, v, o);
    return v;
}

// ---- tf32 helpers ---------------------------------------------------------
__device__ __forceinline__ uint32 tf32_of(float x) {
    uint32 u;
    asm("cvt.rna.tf32.f32 %0, %1;" : "=r"(u) : "f"(x));
    return u;
}
__device__ __forceinline__ void split_tf32(float x, uint32& hi, uint32& lo) {
    hi = tf32_of(x);
    lo = tf32_of(x - __uint_as_float(hi));
}
__device__ __forceinline__ void mma_tf32(float4& d,
                                         uint32 a0, uint32 a1, uint32 a2, uint32 a3,
                                         uint32 b0, uint32 b1) {
    asm("mma.sync.aligned.m16n8k8.row.col.f32.tf32.tf32.f32 "
        "{%0,%1,%2,%3},{%4,%5,%6,%7},{%8,%9},{%0,%1,%2,%3};"
        : "+f"(d.x), "+f"(d.y), "+f"(d.z), "+f"(d.w)
        : "r"(a0), "r"(a1), "r"(a2), "r"(a3), "r"(b0), "r"(b1));
}

// ---------------------------------------------------------------------------
// K0: zero accumulators
// ---------------------------------------------------------------------------
__global__ void k_zero(int n) {
    int i = blockIdx.x * blockDim.x + threadIdx.x;
    if (i < n * 8) g_agg[i] = 0.f;
    if (i < n) { g_degD[i] = 0; g_degR[i] = 0; }
    if (i < 64) g_colsum[i] = 0.f;
}

// ---------------------------------------------------------------------------
// K1: data->task scatter-add (v4 red) + tt degree histograms (fused)
// ---------------------------------------------------------------------------
__global__ void k_edges_pre(const float* __restrict__ data_x,
                            const int* __restrict__ dsrc, const int* __restrict__ ddst,
                            int e_dt,
                            const int* __restrict__ tsrc, const int* __restrict__ tdst,
                            int e_tt) {
    int e = blockIdx.x * blockDim.x + threadIdx.x;
    if (e < e_dt) {
        int s = __ldg(&dsrc[e]);
        int d = __ldg(&ddst[e]);
        const float* xr = data_x + s * 5;
        float x0 = __ldg(&xr[0]), x1 = __ldg(&xr[1]), x2 = __ldg(&xr[2]);
        float x3 = __ldg(&xr[3]), x4 = __ldg(&xr[4]);
        float* ar = g_agg + d * 8;     // 32B-aligned row
        asm volatile("red.global.add.v4.f32 [%0], {%1,%2,%3,%4};"
                     :: "l"(ar), "f"(x0), "f"(x1), "f"(x2), "f"(x3) : "memory");
        atomicAdd(ar + 4, x4);
    }
    if (e < e_tt) {
        atomicAdd(&g_degD[__ldg(&tdst[e])], 1);
        atomicAdd(&g_degR[__ldg(&tsrc[e])], 1);
    }
}

// ---------------------------------------------------------------------------
// Scan stage 1
// ---------------------------------------------------------------------------
__global__ __launch_bounds__(256) void k_scan_blk(int n) {
    int arr = blockIdx.y;
    const int* deg = arr ? g_degR : g_degD;
    int* ptr = arr ? g_ptrR : g_ptrD;
    int* bsum = arr ? g_bsumR : g_bsumD;
    __shared__ int sh[256];
    int tid = threadIdx.x;
    int base = blockIdx.x * 1024;
    int v[4]; int s = 0;
#pragma unroll
    for (int j = 0; j < 4; j++) {
        int idx = base + tid * 4 + j;
        v[j] = (idx < n) ? deg[idx] : 0;
        s += v[j];
    }
    sh[tid] = s;
    __syncthreads();
#pragma unroll
    for (int d = 1; d < 256; d <<= 1) {
        int t = 0;
        if (tid >= d) t = sh[tid - d];
        __syncthreads();
        sh[tid] += t;
        __syncthreads();
    }
    int off = sh[tid] - s;
#pragma unroll
    for (int j = 0; j < 4; j++) {
        int idx = base + tid * 4 + j;
        if (idx < n) ptr[idx] = off;
        off += v[j];
    }
    if (tid == 0) bsum[blockIdx.x] = sh[255];
}

// ---------------------------------------------------------------------------
// Scan stage 2: warp-parallel scan of block sums (one warp per array)
// ---------------------------------------------------------------------------
__global__ void k_scan_top(int nblk) {
    int lane = threadIdx.x & 31;
    int* bs = (threadIdx.x < 32) ? g_bsumD : g_bsumR;
    int base = 0;
    for (int i0 = 0; i0 < nblk; i0 += 32) {
        int idx = i0 + lane;
        int v = (idx < nblk) ? bs[idx] : 0;
        int incl = v;
#pragma unroll
        for (int o = 1; o < 32; o <<= 1) {
            int t = __shfl_up_sync(0xffffffffu, incl, o);
            if (lane >= o) incl += t;
        }
        if (idx < nblk) bs[idx] = base + incl - v;
        base += __shfl_sync(0xffffffffu, incl, 31);
    }
}

// ---------------------------------------------------------------------------
// Scan stage 3
// ---------------------------------------------------------------------------
__global__ __launch_bounds__(256) void k_scan_fix(int n, int E) {
    int arr = blockIdx.y;
    int* ptr = arr ? g_ptrR : g_ptrD;
    int* cur = arr ? g_curR : g_curD;
    const int* bsum = arr ? g_bsumR : g_bsumD;
    int off = bsum[blockIdx.x];
    int base = blockIdx.x * 1024 + threadIdx.x * 4;
#pragma unroll
    for (int j = 0; j < 4; j++) {
        int idx = base + j;
        if (idx < n) { int v = ptr[idx] + off; ptr[idx] = v; cur[idx] = v; }
    }
    if (blockIdx.x == 0 && threadIdx.x == 0) ptr[n] = E;
}

// ---------------------------------------------------------------------------
// K1c: scatter edges into CSR
// ---------------------------------------------------------------------------
__global__ void k_scatter(const int* __restrict__ tsrc, const int* __restrict__ tdst, int E) {
    int e = blockIdx.x * blockDim.x + threadIdx.x;
    if (e >= E) return;
    int s = __ldg(&tsrc[e]);
    int d = __ldg(&tdst[e]);
    int p = atomicAdd(&g_curD[d], 1);
    g_srcD[p] = s;
    int q = atomicAdd(&g_curR[s], 1);
    g_srcR[q] = d;
}

// ---------------------------------------------------------------------------
// K2: fused = leaky(LN(agg @ Wrel + brel + tasks @ Wroot))   (warp per row)
// ---------------------------------------------------------------------------
__global__ void k_fused(const float* __restrict__ tasks_x,
                        const float* __restrict__ Wrel, const float* __restrict__ brel,
                        const float* __restrict__ Wroot,
                        const float* __restrict__ lng, const float* __restrict__ lnb,
                        int n) {
    int gt = blockIdx.x * blockDim.x + threadIdx.x;
    int r = gt >> 5, lane = gt & 31;
    if (r >= n) return;
    float p0 = __ldg(&brel[lane]);
    float p1 = __ldg(&brel[lane + 32]);
    const float* ar = g_agg + r * 8;
#pragma unroll
    for (int k = 0; k < 5; k++) {
        float a = ar[k];
        p0 += a * __ldg(&Wrel[k * 64 + lane]);
        p1 += a * __ldg(&Wrel[k * 64 + lane + 32]);
    }
    const float* tr = tasks_x + r * 12;
#pragma unroll
    for (int k = 0; k < 12; k++) {
        float t = __ldg(&tr[k]);
        p0 += t * __ldg(&Wroot[k * 64 + lane]);
        p1 += t * __ldg(&Wroot[k * 64 + lane + 32]);
    }
    float m = warp_sum(p0 + p1) * (1.f / 64.f);
    float d0 = p0 - m, d1 = p1 - m;
    float v = warp_sum(d0 * d0 + d1 * d1) * (1.f / 64.f);
    float inv = rsqrtf(v + 1e-5f);
    float y0 = leaky(d0 * inv * __ldg(&lng[lane])      + __ldg(&lnb[lane]));
    float y1 = leaky(d1 * inv * __ldg(&lng[lane + 32]) + __ldg(&lnb[lane + 32]));
    g_fused[r * 64 + lane]      = y0;
    g_fused[r * 64 + lane + 32] = y1;
}

// ---------------------------------------------------------------------------
// K3: tensor-core B/C GEMMs (3xTF32, on-the-fly split), both convs, one launch.
// Block = 128 rows, 256 threads. Warp: m0=(wid&3)*32 rows, nhalf=(wid>>2)*64.
// smem floats: Xs [128][68]=8704 | WsD [64][136]=8704 | WsR 8704  (104 KB)
// ---------------------------------------------------------------------------
__global__ __launch_bounds__(256, 2) void k_gemm_tc(
    const float* __restrict__ depW1, const float* __restrict__ revW1, int n) {
    extern __shared__ float sm[];
    float* Xs  = sm;            // [128][68]
    float* WsD = sm + 8704;     // [64][136]
    float* WsR = sm + 17408;    // [64][136]
    int tid = threadIdx.x;
    int row0 = blockIdx.x * 128;

    for (int idx = tid; idx < 8192; idx += 256) {
        int k = idx >> 7, j = idx & 127;
        float wBd = depW1[(64 + k) * 64 + (j & 63)];
        WsD[k * 136 + j] = (j < 64) ? wBd : (depW1[k * 64 + (j - 64)] - wBd);
        float wBr = revW1[(64 + k) * 64 + (j & 63)];
        WsR[k * 136 + j] = (j < 64) ? wBr : (revW1[k * 64 + (j - 64)] - wBr);
    }
#pragma unroll
    for (int it = 0; it < 8; it++) {
        int fi = tid + it * 256;
        int r = fi >> 4, c4 = (fi & 15) * 4;
        float4 v = make_float4(0.f, 0.f, 0.f, 0.f);
        int row = row0 + r;
        if (row < n) v = *reinterpret_cast<const float4*>(&g_fused[row * 64 + c4]);
        *reinterpret_cast<float4*>(&Xs[r * 68 + c4]) = v;
    }
    __syncthreads();

    int lane = tid & 31, wid = tid >> 5;
    int gid = lane >> 2, tig = lane & 3;
    int m0 = (wid & 3) * 32;
    int nhalf = (wid >> 2) * 64;

#pragma unroll 1
    for (int conv = 0; conv < 2; conv++) {
        const float* Ws = conv ? WsR : WsD;
        float4 acc[2][8];
#pragma unroll
        for (int mt = 0; mt < 2; mt++)
#pragma unroll
            for (int nt = 0; nt < 8; nt++) acc[mt][nt] = make_float4(0.f, 0.f, 0.f, 0.f);

#pragma unroll
        for (int ks = 0; ks < 8; ks++) {
            int kb = ks * 8;
            uint32 ah[2][4], al[2][4];
#pragma unroll
            for (int mt = 0; mt < 2; mt++) {
                int rb = m0 + mt * 16;
                split_tf32(Xs[(rb + gid) * 68 + kb + tig],     ah[mt][0], al[mt][0]);
                split_tf32(Xs[(rb + gid + 8) * 68 + kb + tig], ah[mt][1], al[mt][1]);
                split_tf32(Xs[(rb + gid) * 68 + kb + tig + 4],     ah[mt][2], al[mt][2]);
                split_tf32(Xs[(rb + gid + 8) * 68 + kb + tig + 4], ah[mt][3], al[mt][3]);
            }
#pragma unroll
            for (int nt = 0; nt < 8; nt++) {
                int nc = nhalf + nt * 8 + gid;
                uint32 bh0, bl0, bh1, bl1;
                split_tf32(Ws[(kb + tig) * 136 + nc],     bh0, bl0);
                split_tf32(Ws[(kb + tig + 4) * 136 + nc], bh1, bl1);
#pragma unroll
                for (int mt = 0; mt < 2; mt++) {
                    mma_tf32(acc[mt][nt], ah[mt][0], ah[mt][1], ah[mt][2], ah[mt][3], bh0, bh1);
                    mma_tf32(acc[mt][nt], ah[mt][0], ah[mt][1], ah[mt][2], ah[mt][3], bl0, bl1);
                    mma_tf32(acc[mt][nt], al[mt][0], al[mt][1], al[mt][2], al[mt][3], bh0, bh1);
                }
            }
        }

        float* O = (nhalf == 0) ? (conv ? g_Brev : g_Bdep) : (conv ? g_Crev : g_Cdep);
#pragma unroll
        for (int mt = 0; mt < 2; mt++) {
#pragma unroll
            for (int nt = 0; nt < 8; nt++) {
                int c = nt * 8 + tig * 2;
                int rowA = row0 + m0 + mt * 16 + gid;
                int rowB = rowA + 8;
                if (rowA < n)
                    *reinterpret_cast<float2*>(&O[rowA * 64 + c]) =
                        make_float2(acc[mt][nt].x, acc[mt][nt].y);
                if (rowB < n)
                    *reinterpret_cast<float2*>(&O[rowB * 64 + c]) =
                        make_float2(acc[mt][nt].z, acc[mt][nt].w);
            }
        }
    }
}

// ---------------------------------------------------------------------------
// K4: edge aggregation, both convs in one launch (blockIdx.y = conv) — R6 form.
// ---------------------------------------------------------------------------
__global__ __launch_bounds__(256) void k_agg(const float* __restrict__ depb1,
                                             const float* __restrict__ revb1,
                                             int n) {
    int conv = blockIdx.y;
    const int* ptr  = conv ? g_ptrR : g_ptrD;
    const int* srcA = conv ? g_srcR : g_srcD;
    const float* B  = conv ? g_Brev : g_Bdep;
    const float* C  = conv ? g_Crev : g_Cdep;
    const float* b1 = conv ? revb1 : depb1;
    float* S        = conv ? g_Srev : g_Sdep;
    const unsigned FULL = 0xffffffffu;
    int lane = threadIdx.x & 31, wid = threadIdx.x >> 5;
    int r = blockIdx.x * 8 + wid;
    if (r >= n) return;
    int a0 = ptr[r], a1 = ptr[r + 1];
    float2 cv = *reinterpret_cast<const float2*>(&C[r * 64 + 2 * lane]);
    float c0 = cv.x + __ldg(&b1[2 * lane]);
    float c1 = cv.y + __ldg(&b1[2 * lane + 1]);
    float s0 = 0.f, s1 = 0.f;
    for (int i0 = a0; i0 < a1; i0 += 32) {
        int cnt = min(32, a1 - i0);
        int mi = (lane < cnt) ? srcA[i0 + lane] : 0;
        int j = 0;
        for (; j + 4 <= cnt; j += 4) {
            int x0 = __shfl_sync(FULL, mi, j);
            int x1 = __shfl_sync(FULL, mi, j + 1);
            int x2 = __shfl_sync(FULL, mi, j + 2);
            int x3 = __shfl_sync(FULL, mi, j + 3);
            float2 b0 = *reinterpret_cast<const float2*>(&B[x0 * 64 + 2 * lane]);
            float2 b1v = *reinterpret_cast<const float2*>(&B[x1 * 64 + 2 * lane]);
            float2 b2 = *reinterpret_cast<const float2*>(&B[x2 * 64 + 2 * lane]);
            float2 b3 = *reinterpret_cast<const float2*>(&B[x3 * 64 + 2 * lane]);
            s0 += leaky(c0 + b0.x) + leaky(c0 + b1v.x) + leaky(c0 + b2.x) + leaky(c0 + b3.x);
            s1 += leaky(c1 + b0.y) + leaky(c1 + b1v.y) + leaky(c1 + b2.y) + leaky(c1 + b3.y);
        }
        for (; j < cnt; j++) {
            int xs = __shfl_sync(FULL, mi, j);
            float2 b = *reinterpret_cast<const float2*>(&B[xs * 64 + 2 * lane]);
            s0 += leaky(c0 + b.x);
            s1 += leaky(c1 + b.y);
        }
    }
    *reinterpret_cast<float2*>(&S[r * 64 + 2 * lane]) = make_float2(s0, s1);
}

// ---------------------------------------------------------------------------
// K5: tiled tail, TC GEMMs (3xTF32 on-the-fly split) — exact 824us version.
// ---------------------------------------------------------------------------
#define TS 68

__global__ __launch_bounds__(256) void k_tail2(
    const float* __restrict__ depW2, const float* __restrict__ depb2,
    const float* __restrict__ depg,  const float* __restrict__ depb,
    const float* __restrict__ revW2, const float* __restrict__ revb2,
    const float* __restrict__ revg,  const float* __restrict__ revb,
    const float* __restrict__ projW, const float* __restrict__ projb,
    float* __restrict__ out, int n) {
    extern __shared__ float sm[];
    float* W  = sm;            // [128][72]
    float* Xs = sm + 9216;     // [128][68]
    float* Dp = sm + 17920;
    float* Rv = sm + 26624;
    float* V  = sm + 35328;    // 448
    float* CP = sm + 35776;    // 512
    float* DG = sm + 36288;    // 256

    int tid = threadIdx.x;
    int row0 = blockIdx.x * 128;
    int lane = tid & 31, wid = tid >> 5;
    int gid = lane >> 2, tig = lane & 3;
    int m0 = wid * 16;
    const unsigned FULL = 0xffffffffu;

    if (tid < 64) {
        V[tid]       = depb2[tid];
        V[64 + tid]  = revb2[tid];
        V[128 + tid] = depg[tid];
        V[192 + tid] = depb[tid];
        V[256 + tid] = revg[tid];
        V[320 + tid] = revb[tid];
        V[384 + tid] = projb[tid];
    }
    if (tid < 128) {
        int row = row0 + tid;
        DG[tid]       = (row < n) ? (float)(g_ptrD[row + 1] - g_ptrD[row]) : 0.f;
        DG[128 + tid] = (row < n) ? (float)(g_ptrR[row + 1] - g_ptrR[row]) : 0.f;
    }

    // ============ stage 1: dep ============
    for (int i = tid; i < 4096; i += 256) W[(i >> 6) * 72 + (i & 63)] = depW2[i];
#pragma unroll
    for (int it = 0; it < 8; it++) {
        int fi = tid + it * 256;
        int r = fi >> 4, c4 = (fi & 15) * 4;
        float4 v = make_float4(0.f, 0.f, 0.f, 0.f);
        int row = row0 + r;
        if (row < n) v = *reinterpret_cast<const float4*>(&g_Sdep[row * 64 + c4]);
        *reinterpret_cast<float4*>(&Xs[r * TS + c4]) = v;
    }
    __syncthreads();

    {
        float4 acc[8];
#pragma unroll
        for (int nt = 0; nt < 8; nt++) acc[nt] = make_float4(0.f, 0.f, 0.f, 0.f);
#pragma unroll
        for (int ks = 0; ks < 8; ks++) {
            int kb = ks * 8;
            uint32 ah[4], al[4];
            split_tf32(Xs[(m0 + gid) * TS + kb + tig],     ah[0], al[0]);
            split_tf32(Xs[(m0 + gid + 8) * TS + kb + tig], ah[1], al[1]);
            split_tf32(Xs[(m0 + gid) * TS + kb + tig + 4],     ah[2], al[2]);
            split_tf32(Xs[(m0 + gid + 8) * TS + kb + tig + 4], ah[3], al[3]);
#pragma unroll
            for (int nt = 0; nt < 8; nt++) {
                int nc = nt * 8 + gid;
                uint32 bh0, bl0, bh1, bl1;
                split_tf32(W[(kb + tig) * 72 + nc],     bh0, bl0);
                split_tf32(W[(kb + tig + 4) * 72 + nc], bh1, bl1);
                mma_tf32(acc[nt], ah[0], ah[1], ah[2], ah[3], bh0, bh1);
                mma_tf32(acc[nt], ah[0], ah[1], ah[2], ah[3], bl0, bl1);
                mma_tf32(acc[nt], al[0], al[1], al[2], al[3], bh0, bh1);
            }
        }
        float dgA = DG[m0 + gid], dgB = DG[m0 + gid + 8];
#pragma unroll
        for (int nt = 0; nt < 8; nt++) {
            int c = nt * 8 + tig * 2;
            Dp[(m0 + gid) * TS + c]     = acc[nt].x + dgA * V[c];
            Dp[(m0 + gid) * TS + c + 1] = acc[nt].y + dgA * V[c + 1];
            Dp[(m0 + gid + 8) * TS + c]     = acc[nt].z + dgB * V[c];
            Dp[(m0 + gid + 8) * TS + c + 1] = acc[nt].w + dgB * V[c + 1];
        }
    }
    __syncthreads();

    // LN dep; concurrently stage W2r + load S_rev
#pragma unroll
    for (int t = 0; t < 16; t++) {
        int row = wid * 16 + t;
        float h0 = Dp[row * TS + lane];
        float h1 = Dp[row * TS + 32 + lane];
        float m = warp_sum(h0 + h1) * (1.f / 64.f);
        float e0 = h0 - m, e1 = h1 - m;
        float v = warp_sum(e0 * e0 + e1 * e1) * (1.f / 64.f);
        float inv = rsqrtf(v + 1e-5f);
        Dp[row * TS + lane]      = leaky(e0 * inv * V[128 + lane] + V[192 + lane]);
        Dp[row * TS + 32 + lane] = leaky(e1 * inv * V[160 + lane] + V[224 + lane]);
    }
    for (int i = tid; i < 4096; i += 256) W[(i >> 6) * 72 + (i & 63)] = revW2[i];
#pragma unroll
    for (int it = 0; it < 8; it++) {
        int fi = tid + it * 256;
        int r = fi >> 4, c4 = (fi & 15) * 4;
        float4 v = make_float4(0.f, 0.f, 0.f, 0.f);
        int row = row0 + r;
        if (row < n) v = *reinterpret_cast<const float4*>(&g_Srev[row * 64 + c4]);
        *reinterpret_cast<float4*>(&Xs[r * TS + c4]) = v;
    }
    __syncthreads();

    // ============ stage 2: rev ============
    {
        float4 acc[8];
#pragma unroll
        for (int nt = 0; nt < 8; nt++) acc[nt] = make_float4(0.f, 0.f, 0.f, 0.f);
#pragma unroll
        for (int ks = 0; ks < 8; ks++) {
            int kb = ks * 8;
            uint32 ah[4], al[4];
            split_tf32(Xs[(m0 + gid) * TS + kb + tig],     ah[0], al[0]);
            split_tf32(Xs[(m0 + gid + 8) * TS + kb + tig], ah[1], al[1]);
            split_tf32(Xs[(m0 + gid) * TS + kb + tig + 4],     ah[2], al[2]);
            split_tf32(Xs[(m0 + gid + 8) * TS + kb + tig + 4], ah[3], al[3]);
#pragma unroll
            for (int nt = 0; nt < 8; nt++) {
                int nc = nt * 8 + gid;
                uint32 bh0, bl0, bh1, bl1;
                split_tf32(W[(kb + tig) * 72 + nc],     bh0, bl0);
                split_tf32(W[(kb + tig + 4) * 72 + nc], bh1, bl1);
                mma_tf32(acc[nt], ah[0], ah[1], ah[2], ah[3], bh0, bh1);
                mma_tf32(acc[nt], ah[0], ah[1], ah[2], ah[3], bl0, bl1);
                mma_tf32(acc[nt], al[0], al[1], al[2], al[3], bh0, bh1);
            }
        }
        float dgA = DG[128 + m0 + gid], dgB = DG[128 + m0 + gid + 8];
#pragma unroll
        for (int nt = 0; nt < 8; nt++) {
            int c = nt * 8 + tig * 2;
            Rv[(m0 + gid) * TS + c]     = acc[nt].x + dgA * V[64 + c];
            Rv[(m0 + gid) * TS + c + 1] = acc[nt].y + dgA * V[64 + c + 1];
            Rv[(m0 + gid + 8) * TS + c]     = acc[nt].z + dgB * V[64 + c];
            Rv[(m0 + gid + 8) * TS + c + 1] = acc[nt].w + dgB * V[64 + c + 1];
        }
    }
    __syncthreads();

    // LN rev; concurrently stage P
#pragma unroll
    for (int t = 0; t < 16; t++) {
        int row = wid * 16 + t;
        float h0 = Rv[row * TS + lane];
        float h1 = Rv[row * TS + 32 + lane];
        float m = warp_sum(h0 + h1) * (1.f / 64.f);
        float e0 = h0 - m, e1 = h1 - m;
        float v = warp_sum(e0 * e0 + e1 * e1) * (1.f / 64.f);
        float inv = rsqrtf(v + 1e-5f);
        Rv[row * TS + lane]      = leaky(e0 * inv * V[256 + lane] + V[320 + lane]);
        Rv[row * TS + 32 + lane] = leaky(e1 * inv * V[288 + lane] + V[352 + lane]);
    }
    for (int i = tid; i < 8192; i += 256) W[(i >> 6) * 72 + (i & 63)] = projW[i];
    __syncthreads();

    // ============ stage 3: proj + reduce ============
    {
        float4 acc[8];
#pragma unroll
        for (int nt = 0; nt < 8; nt++) acc[nt] = make_float4(0.f, 0.f, 0.f, 0.f);
#pragma unroll
        for (int ks = 0; ks < 16; ks++) {
            const float* A = (ks < 8) ? Dp : Rv;
            int kb = (ks & 7) * 8;
            uint32 ah[4], al[4];
            split_tf32(A[(m0 + gid) * TS + kb + tig],     ah[0], al[0]);
            split_tf32(A[(m0 + gid + 8) * TS + kb + tig], ah[1], al[1]);
            split_tf32(A[(m0 + gid) * TS + kb + tig + 4],     ah[2], al[2]);
            split_tf32(A[(m0 + gid + 8) * TS + kb + tig + 4], ah[3], al[3]);
#pragma unroll
            for (int nt = 0; nt < 8; nt++) {
                int nc = nt * 8 + gid;
                uint32 bh0, bl0, bh1, bl1;
                split_tf32(W[(ks * 8 + tig) * 72 + nc],     bh0, bl0);
                split_tf32(W[(ks * 8 + tig + 4) * 72 + nc], bh1, bl1);
                mma_tf32(acc[nt], ah[0], ah[1], ah[2], ah[3], bh0, bh1);
                mma_tf32(acc[nt], ah[0], ah[1], ah[2], ah[3], bl0, bl1);
                mma_tf32(acc[nt], al[0], al[1], al[2], al[3], bh0, bh1);
            }
        }
        int rowA = row0 + m0 + gid;
        int rowB = rowA + 8;
#pragma unroll
        for (int nt = 0; nt < 8; nt++) {
            int c = nt * 8 + tig * 2;
            float t0 = leaky(acc[nt].x + V[384 + c]);
            float t1 = leaky(acc[nt].y + V[384 + c + 1]);
            float t2 = leaky(acc[nt].z + V[384 + c]);
            float t3 = leaky(acc[nt].w + V[384 + c + 1]);
            float sx = ((rowA < n) ? t0 : 0.f) + ((rowB < n) ? t2 : 0.f);
            float sy = ((rowA < n) ? t1 : 0.f) + ((rowB < n) ? t3 : 0.f);
            sx += __shfl_xor_sync(FULL, sx, 4);
            sy += __shfl_xor_sync(FULL, sy, 4);
            sx += __shfl_xor_sync(FULL, sx, 8);
            sy += __shfl_xor_sync(FULL, sy, 8);
            sx += __shfl_xor_sync(FULL, sx, 16);
            sy += __shfl_xor_sync(FULL, sy, 16);
            if (gid == 0) {
                CP[wid * 64 + c]     = sx;
                CP[wid * 64 + c + 1] = sy;
            }
            if (rowA == 0) {
                out[64 + c]     = t0;
                out[64 + c + 1] = t1;
            }
        }
    }
    __syncthreads();
    if (tid < 64) {
        float s = 0.f;
#pragma unroll
        for (int g = 0; g < 8; g++) s += CP[g * 64 + tid];
        atomicAdd(&g_colsum[tid], s);
    }
}

// ---------------------------------------------------------------------------
// K6: finalize
// ---------------------------------------------------------------------------
__global__ void k_final(const int* __restrict__ counts,
                        const float* __restrict__ devx,
                        const float* __restrict__ timex,
                        const float* __restrict__ devW,
                        const float* __restrict__ devb,
                        float* __restrict__ out) {
    int tid = threadIdx.x;
    if (tid < 64) {
        int c = counts[0];
        if (c < 1) c = 1;
        out[tid] = g_colsum[tid] / (float)c;
    } else if (tid < 128) {
        int j = tid - 64;
        float p = devb[j];
#pragma unroll 8
        for (int k = 0; k < 96; k++) p += devx[k] * devW[k * 64 + j];
        p += (timex[0] * 1e-5f) * devW[96 * 64 + j];
        out[128 + j] = leaky(p);
    }
}

// ---------------------------------------------------------------------------
// Launch.  Order puts k_gemm_tc at slot 4 (the ncu-captured launch) for
// attribution; scan/CSR chain is independent and moved after it.
// ---------------------------------------------------------------------------
extern "C" void kernel_launch(void* const* d_in, const int* in_sizes, int n_in,
                              void* d_out, int out_size) {
    const float* data_x    = (const float*)d_in[0];
    const float* tasks_x   = (const float*)d_in[1];
    const float* devices_x = (const float*)d_in[2];
    const float* time_x    = (const float*)d_in[3];
    const int*   dt_src    = (const int*)d_in[4];
    const int*   dt_dst    = (const int*)d_in[5];
    const int*   tt_src    = (const int*)d_in[6];
    const int*   tt_dst    = (const int*)d_in[7];
    const int*   counts    = (const int*)d_in[8];
    const float* gcWrel    = (const float*)d_in[9];
    const float* gcbrel    = (const float*)d_in[10];
    const float* gcWroot   = (const float*)d_in[11];
    const float* gclng     = (const float*)d_in[12];
    const float* gclnb     = (const float*)d_in[13];
    const float* depW1     = (const float*)d_in[14];
    const float* depb1     = (const float*)d_in[15];
    const float* depW2     = (const float*)d_in[16];
    const float* depb2     = (const float*)d_in[17];
    const float* deplng    = (const float*)d_in[18];
    const float* deplnb    = (const float*)d_in[19];
    const float* revW1     = (const float*)d_in[20];
    const float* revb1     = (const float*)d_in[21];
    const float* revW2     = (const float*)d_in[22];
    const float* revb2     = (const float*)d_in[23];
    const float* revlng    = (const float*)d_in[24];
    const float* revlnb    = (const float*)d_in[25];
    const float* devW      = (const float*)d_in[26];
    const float* devb      = (const float*)d_in[27];
    const float* projW     = (const float*)d_in[28];
    const float* projb     = (const float*)d_in[29];
    float* out = (float*)d_out;

    int n    = in_sizes[1] / 12;
    int e_dt = in_sizes[4];
    int e_tt = in_sizes[6];
    int nblk = (n + 1023) / 1024;
    int emax = e_dt > e_tt ? e_dt : e_tt;

    cudaFuncSetAttribute(k_gemm_tc, cudaFuncAttributeMaxDynamicSharedMemorySize, 104448);
    cudaFuncSetAttribute(k_tail2,   cudaFuncAttributeMaxDynamicSharedMemorySize, 146176);

    int gb = (n + 127) / 128;

    k_zero<<<(n * 8 + 255) / 256, 256>>>(n);                                     // 1
    k_edges_pre<<<(emax + 255) / 256, 256>>>(data_x, dt_src, dt_dst, e_dt,
                                             tt_src, tt_dst, e_tt);              // 2
    k_fused<<<(n * 32 + 255) / 256, 256>>>(tasks_x, gcWrel, gcbrel, gcWroot,
                                           gclng, gclnb, n);                     // 3
    k_gemm_tc<<<gb, 256, 104448>>>(depW1, revW1, n);                             // 4 <- profiled

    dim3 sg(nblk, 2);
    k_scan_blk<<<sg, 256>>>(n);                                                  // 5
    k_scan_top<<<1, 64>>>(nblk);                                                 // 6
    k_scan_fix<<<sg, 256>>>(n, e_tt);                                            // 7
    k_scatter<<<(e_tt + 255) / 256, 256>>>(tt_src, tt_dst, e_tt);                // 8

    dim3 ag((n + 7) / 8, 2);
    k_agg<<<ag, 256>>>(depb1, revb1, n);                                         // 9

    k_tail2<<<gb, 256, 146176>>>(depW2, depb2, deplng, deplnb,
                                 revW2, revb2, revlng, revlnb,
                                 projW, projb, out, n);                          // 10
    k_final<<<1, 128>>>(counts, devices_x, time_x, devW, devb, out);             // 11
}

// round 14
// speedup vs baseline: 1.9455x; 1.0949x over previous
#include <cuda_runtime.h>

#define NT_MAX 200000
#define ETT_MAX 1100000

typedef unsigned int uint32;

// ---------------------------------------------------------------------------
// Scratch (__device__ globals — allocation-free rule)
// ---------------------------------------------------------------------------
__device__ float g_agg  [NT_MAX * 8];   // padded row stride 8 for v4 red atomics
__device__ float g_fused[NT_MAX * 64];
__device__ float g_Bdep [NT_MAX * 64];
__device__ float g_Cdep [NT_MAX * 64];
__device__ float g_Brev [NT_MAX * 64];
__device__ float g_Crev [NT_MAX * 64];
__device__ float g_Sdep [NT_MAX * 64];
__device__ float g_Srev [NT_MAX * 64];
__device__ int   g_degD [NT_MAX];
__device__ int   g_degR [NT_MAX];
__device__ int   g_ptrD [NT_MAX + 1];
__device__ int   g_ptrR [NT_MAX + 1];
__device__ int   g_curD [NT_MAX];
__device__ int   g_curR [NT_MAX];
__device__ int   g_srcD [ETT_MAX];
__device__ int   g_srcR [ETT_MAX];
__device__ int   g_bsumD[512];
__device__ int   g_bsumR[512];
__device__ float g_colsum[64];

__device__ __forceinline__ float leaky(float x) { return x > 0.f ? x : 0.01f * x; }

__device__ __forceinline__ float warp_sum(float v) {
#pragma unroll
    for (int o = 16; o > 0; o >>= 1) v += __shfl_xor_sync(0xffffffffu, v, o);
    return v;
}

// ---- tf32 helpers ---------------------------------------------------------
__device__ __forceinline__ uint32 tf32_of(float x) {
    uint32 u;
    asm("cvt.rna.tf32.f32 %0, %1;" : "=r"(u) : "f"(x));
    return u;
}
__device__ __forceinline__ void split_tf32(float x, uint32& hi, uint32& lo) {
    hi = tf32_of(x);
    lo = tf32_of(x - __uint_as_float(hi));
}
__device__ __forceinline__ void mma_tf32(float4& d,
                                         uint32 a0, uint32 a1, uint32 a2, uint32 a3,
                                         uint32 b0, uint32 b1) {
    asm("mma.sync.aligned.m16n8k8.row.col.f32.tf32.tf32.f32 "
        "{%0,%1,%2,%3},{%4,%5,%6,%7},{%8,%9},{%0,%1,%2,%3};"
        : "+f"(d.x), "+f"(d.y), "+f"(d.z), "+f"(d.w)
        : "r"(a0), "r"(a1), "r"(a2), "r"(a3), "r"(b0), "r"(b1));
}

// ---------------------------------------------------------------------------
// K0: zero accumulators
// ---------------------------------------------------------------------------
__global__ void k_zero(int n) {
    int i = blockIdx.x * blockDim.x + threadIdx.x;
    if (i < n * 8) g_agg[i] = 0.f;
    if (i < n) { g_degD[i] = 0; g_degR[i] = 0; }
    if (i < 64) g_colsum[i] = 0.f;
}

// ---------------------------------------------------------------------------
// K1: data->task scatter-add (v4 red) + tt degree histograms (fused)
// ---------------------------------------------------------------------------
__global__ void k_edges_pre(const float* __restrict__ data_x,
                            const int* __restrict__ dsrc, const int* __restrict__ ddst,
                            int e_dt,
                            const int* __restrict__ tsrc, const int* __restrict__ tdst,
                            int e_tt) {
    int e = blockIdx.x * blockDim.x + threadIdx.x;
    if (e < e_dt) {
        int s = __ldg(&dsrc[e]);
        int d = __ldg(&ddst[e]);
        const float* xr = data_x + s * 5;
        float x0 = __ldg(&xr[0]), x1 = __ldg(&xr[1]), x2 = __ldg(&xr[2]);
        float x3 = __ldg(&xr[3]), x4 = __ldg(&xr[4]);
        float* ar = g_agg + d * 8;
        asm volatile("red.global.add.v4.f32 [%0], {%1,%2,%3,%4};"
                     :: "l"(ar), "f"(x0), "f"(x1), "f"(x2), "f"(x3) : "memory");
        atomicAdd(ar + 4, x4);
    }
    if (e < e_tt) {
        atomicAdd(&g_degD[__ldg(&tdst[e])], 1);
        atomicAdd(&g_degR[__ldg(&tsrc[e])], 1);
    }
}

// ---------------------------------------------------------------------------
// Scan stage 1
// ---------------------------------------------------------------------------
__global__ __launch_bounds__(256) void k_scan_blk(int n) {
    int arr = blockIdx.y;
    const int* deg = arr ? g_degR : g_degD;
    int* ptr = arr ? g_ptrR : g_ptrD;
    int* bsum = arr ? g_bsumR : g_bsumD;
    __shared__ int sh[256];
    int tid = threadIdx.x;
    int base = blockIdx.x * 1024;
    int v[4]; int s = 0;
#pragma unroll
    for (int j = 0; j < 4; j++) {
        int idx = base + tid * 4 + j;
        v[j] = (idx < n) ? deg[idx] : 0;
        s += v[j];
    }
    sh[tid] = s;
    __syncthreads();
#pragma unroll
    for (int d = 1; d < 256; d <<= 1) {
        int t = 0;
        if (tid >= d) t = sh[tid - d];
        __syncthreads();
        sh[tid] += t;
        __syncthreads();
    }
    int off = sh[tid] - s;
#pragma unroll
    for (int j = 0; j < 4; j++) {
        int idx = base + tid * 4 + j;
        if (idx < n) ptr[idx] = off;
        off += v[j];
    }
    if (tid == 0) bsum[blockIdx.x] = sh[255];
}

// ---------------------------------------------------------------------------
// Scan stage 2: warp-parallel scan of block sums (one warp per array)
// ---------------------------------------------------------------------------
__global__ void k_scan_top(int nblk) {
    int lane = threadIdx.x & 31;
    int* bs = (threadIdx.x < 32) ? g_bsumD : g_bsumR;
    int base = 0;
    for (int i0 = 0; i0 < nblk; i0 += 32) {
        int idx = i0 + lane;
        int v = (idx < nblk) ? bs[idx] : 0;
        int incl = v;
#pragma unroll
        for (int o = 1; o < 32; o <<= 1) {
            int t = __shfl_up_sync(0xffffffffu, incl, o);
            if (lane >= o) incl += t;
        }
        if (idx < nblk) bs[idx] = base + incl - v;
        base += __shfl_sync(0xffffffffu, incl, 31);
    }
}

// ---------------------------------------------------------------------------
// Scan stage 3
// ---------------------------------------------------------------------------
__global__ __launch_bounds__(256) void k_scan_fix(int n, int E) {
    int arr = blockIdx.y;
    int* ptr = arr ? g_ptrR : g_ptrD;
    int* cur = arr ? g_curR : g_curD;
    const int* bsum = arr ? g_bsumR : g_bsumD;
    int off = bsum[blockIdx.x];
    int base = blockIdx.x * 1024 + threadIdx.x * 4;
#pragma unroll
    for (int j = 0; j < 4; j++) {
        int idx = base + j;
        if (idx < n) { int v = ptr[idx] + off; ptr[idx] = v; cur[idx] = v; }
    }
    if (blockIdx.x == 0 && threadIdx.x == 0) ptr[n] = E;
}

// ---------------------------------------------------------------------------
// K1c: scatter edges into CSR
// ---------------------------------------------------------------------------
__global__ void k_scatter(const int* __restrict__ tsrc, const int* __restrict__ tdst, int E) {
    int e = blockIdx.x * blockDim.x + threadIdx.x;
    if (e >= E) return;
    int s = __ldg(&tsrc[e]);
    int d = __ldg(&tdst[e]);
    int p = atomicAdd(&g_curD[d], 1);
    g_srcD[p] = s;
    int q = atomicAdd(&g_curR[s], 1);
    g_srcR[q] = d;
}

// ---------------------------------------------------------------------------
// K2: fused = leaky(LN(agg @ Wrel + brel + tasks @ Wroot))   (warp per row)
// ---------------------------------------------------------------------------
__global__ void k_fused(const float* __restrict__ tasks_x,
                        const float* __restrict__ Wrel, const float* __restrict__ brel,
                        const float* __restrict__ Wroot,
                        const float* __restrict__ lng, const float* __restrict__ lnb,
                        int n) {
    int gt = blockIdx.x * blockDim.x + threadIdx.x;
    int r = gt >> 5, lane = gt & 31;
    if (r >= n) return;
    float p0 = __ldg(&brel[lane]);
    float p1 = __ldg(&brel[lane + 32]);
    const float* ar = g_agg + r * 8;
#pragma unroll
    for (int k = 0; k < 5; k++) {
        float a = ar[k];
        p0 += a * __ldg(&Wrel[k * 64 + lane]);
        p1 += a * __ldg(&Wrel[k * 64 + lane + 32]);
    }
    const float* tr = tasks_x + r * 12;
#pragma unroll
    for (int k = 0; k < 12; k++) {
        float t = __ldg(&tr[k]);
        p0 += t * __ldg(&Wroot[k * 64 + lane]);
        p1 += t * __ldg(&Wroot[k * 64 + lane + 32]);
    }
    float m = warp_sum(p0 + p1) * (1.f / 64.f);
    float d0 = p0 - m, d1 = p1 - m;
    float v = warp_sum(d0 * d0 + d1 * d1) * (1.f / 64.f);
    float inv = rsqrtf(v + 1e-5f);
    float y0 = leaky(d0 * inv * __ldg(&lng[lane])      + __ldg(&lnb[lane]));
    float y1 = leaky(d1 * inv * __ldg(&lng[lane + 32]) + __ldg(&lnb[lane + 32]));
    g_fused[r * 64 + lane]      = y0;
    g_fused[r * 64 + lane + 32] = y1;
}

// ---------------------------------------------------------------------------
// K3: tensor-core B/C GEMM (3xTF32), ONE conv per block (blockIdx.y).
// Block = 128 rows, 256 threads, warp = 16 rows x 64 cols, half-loop over
// the 128-wide [B|C] output. smem 69632 B -> 3 blocks/SM.
// ---------------------------------------------------------------------------
__global__ __launch_bounds__(256, 3) void k_gemm_tc(
    const float* __restrict__ depW1, const float* __restrict__ revW1, int n) {
    extern __shared__ float sm[];
    float* Xs = sm;            // [128][68]
    float* Ws = sm + 8704;     // [64][136]
    int tid = threadIdx.x;
    int row0 = blockIdx.x * 128;
    int conv = blockIdx.y;
    const float* W1 = conv ? revW1 : depW1;

    for (int idx = tid; idx < 8192; idx += 256) {
        int k = idx >> 7, j = idx & 127;
        float wB = W1[(64 + k) * 64 + (j & 63)];
        Ws[k * 136 + j] = (j < 64) ? wB : (W1[k * 64 + (j - 64)] - wB);
    }
#pragma unroll
    for (int it = 0; it < 8; it++) {
        int fi = tid + it * 256;
        int r = fi >> 4, c4 = (fi & 15) * 4;
        float4 v = make_float4(0.f, 0.f, 0.f, 0.f);
        int row = row0 + r;
        if (row < n) v = *reinterpret_cast<const float4*>(&g_fused[row * 64 + c4]);
        *reinterpret_cast<float4*>(&Xs[r * 68 + c4]) = v;
    }
    __syncthreads();

    int lane = tid & 31, wid = tid >> 5;
    int gid = lane >> 2, tig = lane & 3;
    int m0 = wid * 16;

#pragma unroll 1
    for (int half = 0; half < 2; half++) {
        float4 acc[8];
#pragma unroll
        for (int nt = 0; nt < 8; nt++) acc[nt] = make_float4(0.f, 0.f, 0.f, 0.f);
#pragma unroll
        for (int ks = 0; ks < 8; ks++) {
            int kb = ks * 8;
            uint32 ah[4], al[4];
            split_tf32(Xs[(m0 + gid) * 68 + kb + tig],     ah[0], al[0]);
            split_tf32(Xs[(m0 + gid + 8) * 68 + kb + tig], ah[1], al[1]);
            split_tf32(Xs[(m0 + gid) * 68 + kb + tig + 4],     ah[2], al[2]);
            split_tf32(Xs[(m0 + gid + 8) * 68 + kb + tig + 4], ah[3], al[3]);
#pragma unroll
            for (int nt = 0; nt < 8; nt++) {
                int nc = half * 64 + nt * 8 + gid;
                uint32 bh0, bl0, bh1, bl1;
                split_tf32(Ws[(kb + tig) * 136 + nc],     bh0, bl0);
                split_tf32(Ws[(kb + tig + 4) * 136 + nc], bh1, bl1);
                mma_tf32(acc[nt], ah[0], ah[1], ah[2], ah[3], bh0, bh1);
                mma_tf32(acc[nt], ah[0], ah[1], ah[2], ah[3], bl0, bl1);
                mma_tf32(acc[nt], al[0], al[1], al[2], al[3], bh0, bh1);
            }
        }
        float* O = (half == 0) ? (conv ? g_Brev : g_Bdep) : (conv ? g_Crev : g_Cdep);
        int rowA = row0 + m0 + gid;
        int rowB = rowA + 8;
#pragma unroll
        for (int nt = 0; nt < 8; nt++) {
            int c = nt * 8 + tig * 2;
            if (rowA < n)
                *reinterpret_cast<float2*>(&O[rowA * 64 + c]) =
                    make_float2(acc[nt].x, acc[nt].y);
            if (rowB < n)
                *reinterpret_cast<float2*>(&O[rowB * 64 + c]) =
                    make_float2(acc[nt].z, acc[nt].w);
        }
    }
}

// ---------------------------------------------------------------------------
// K4: edge aggregation, both convs in one launch (blockIdx.y = conv).
// ---------------------------------------------------------------------------
__global__ __launch_bounds__(256) void k_agg(const float* __restrict__ depb1,
                                             const float* __restrict__ revb1,
                                             int n) {
    int conv = blockIdx.y;
    const int* ptr  = conv ? g_ptrR : g_ptrD;
    const int* srcA = conv ? g_srcR : g_srcD;
    const float* B  = conv ? g_Brev : g_Bdep;
    const float* C  = conv ? g_Crev : g_Cdep;
    const float* b1 = conv ? revb1 : depb1;
    float* S        = conv ? g_Srev : g_Sdep;
    const unsigned FULL = 0xffffffffu;
    int lane = threadIdx.x & 31, wid = threadIdx.x >> 5;
    int r = blockIdx.x * 8 + wid;
    if (r >= n) return;
    int a0 = ptr[r], a1 = ptr[r + 1];
    float2 cv = *reinterpret_cast<const float2*>(&C[r * 64 + 2 * lane]);
    float c0 = cv.x + __ldg(&b1[2 * lane]);
    float c1 = cv.y + __ldg(&b1[2 * lane + 1]);
    float s0 = 0.f, s1 = 0.f;
    for (int i0 = a0; i0 < a1; i0 += 32) {
        int cnt = min(32, a1 - i0);
        int mi = (lane < cnt) ? srcA[i0 + lane] : 0;
        int j = 0;
        for (; j + 4 <= cnt; j += 4) {
            int x0 = __shfl_sync(FULL, mi, j);
            int x1 = __shfl_sync(FULL, mi, j + 1);
            int x2 = __shfl_sync(FULL, mi, j + 2);
            int x3 = __shfl_sync(FULL, mi, j + 3);
            float2 b0 = *reinterpret_cast<const float2*>(&B[x0 * 64 + 2 * lane]);
            float2 b1v = *reinterpret_cast<const float2*>(&B[x1 * 64 + 2 * lane]);
            float2 b2 = *reinterpret_cast<const float2*>(&B[x2 * 64 + 2 * lane]);
            float2 b3 = *reinterpret_cast<const float2*>(&B[x3 * 64 + 2 * lane]);
            s0 += leaky(c0 + b0.x) + leaky(c0 + b1v.x) + leaky(c0 + b2.x) + leaky(c0 + b3.x);
            s1 += leaky(c1 + b0.y) + leaky(c1 + b1v.y) + leaky(c1 + b2.y) + leaky(c1 + b3.y);
        }
        for (; j < cnt; j++) {
            int xs = __shfl_sync(FULL, mi, j);
            float2 b = *reinterpret_cast<const float2*>(&B[xs * 64 + 2 * lane]);
            s0 += leaky(c0 + b.x);
            s1 += leaky(c1 + b.y);
        }
    }
    *reinterpret_cast<float2*>(&S[r * 64 + 2 * lane]) = make_float2(s0, s1);
}

// ---------------------------------------------------------------------------
// K5: tiled tail, TC GEMMs (3xTF32), slimmed smem -> 2 blocks/SM.
// In-place S->H per warp (each warp reads/writes only its own 16 rows).
// W region = [64][72]; projW consumed in two halves.
// smem floats: W 4608 | Dp [128][68] 8704 | Rv 8704 | V 448 | CP 512 | DG 256
//   = 23232 floats = 92928 B
// ---------------------------------------------------------------------------
#define TS 68

__global__ __launch_bounds__(256, 2) void k_tail2(
    const float* __restrict__ depW2, const float* __restrict__ depb2,
    const float* __restrict__ depg,  const float* __restrict__ depb,
    const float* __restrict__ revW2, const float* __restrict__ revb2,
    const float* __restrict__ revg,  const float* __restrict__ revb,
    const float* __restrict__ projW, const float* __restrict__ projb,
    float* __restrict__ out, int n) {
    extern __shared__ float sm[];
    float* W  = sm;            // [64][72]
    float* Dp = sm + 4608;     // [128][68]
    float* Rv = sm + 13312;    // [128][68]
    float* V  = sm + 22016;    // 448
    float* CP = sm + 22464;    // 512
    float* DG = sm + 22976;    // 256

    int tid = threadIdx.x;
    int row0 = blockIdx.x * 128;
    int lane = tid & 31, wid = tid >> 5;
    int gid = lane >> 2, tig = lane & 3;
    int m0 = wid * 16;
    const unsigned FULL = 0xffffffffu;

    if (tid < 64) {
        V[tid]       = depb2[tid];
        V[64 + tid]  = revb2[tid];
        V[128 + tid] = depg[tid];
        V[192 + tid] = depb[tid];
        V[256 + tid] = revg[tid];
        V[320 + tid] = revb[tid];
        V[384 + tid] = projb[tid];
    }
    if (tid < 128) {
        int row = row0 + tid;
        DG[tid]       = (row < n) ? (float)(g_ptrD[row + 1] - g_ptrD[row]) : 0.f;
        DG[128 + tid] = (row < n) ? (float)(g_ptrR[row + 1] - g_ptrR[row]) : 0.f;
    }

    // ============ stage 1: dep ============
    for (int i = tid; i < 4096; i += 256) W[(i >> 6) * 72 + (i & 63)] = depW2[i];
#pragma unroll
    for (int it = 0; it < 8; it++) {
        int fi = tid + it * 256;
        int r = fi >> 4, c4 = (fi & 15) * 4;
        float4 v = make_float4(0.f, 0.f, 0.f, 0.f);
        int row = row0 + r;
        if (row < n) v = *reinterpret_cast<const float4*>(&g_Sdep[row * 64 + c4]);
        *reinterpret_cast<float4*>(&Dp[r * TS + c4]) = v;
    }
    __syncthreads();

    {
        float4 acc[8];
#pragma unroll
        for (int nt = 0; nt < 8; nt++) acc[nt] = make_float4(0.f, 0.f, 0.f, 0.f);
#pragma unroll
        for (int ks = 0; ks < 8; ks++) {
            int kb = ks * 8;
            uint32 ah[4], al[4];
            split_tf32(Dp[(m0 + gid) * TS + kb + tig],     ah[0], al[0]);
            split_tf32(Dp[(m0 + gid + 8) * TS + kb + tig], ah[1], al[1]);
            split_tf32(Dp[(m0 + gid) * TS + kb + tig + 4],     ah[2], al[2]);
            split_tf32(Dp[(m0 + gid + 8) * TS + kb + tig + 4], ah[3], al[3]);
#pragma unroll
            for (int nt = 0; nt < 8; nt++) {
                int nc = nt * 8 + gid;
                uint32 bh0, bl0, bh1, bl1;
                split_tf32(W[(kb + tig) * 72 + nc],     bh0, bl0);
                split_tf32(W[(kb + tig + 4) * 72 + nc], bh1, bl1);
                mma_tf32(acc[nt], ah[0], ah[1], ah[2], ah[3], bh0, bh1);
                mma_tf32(acc[nt], ah[0], ah[1], ah[2], ah[3], bl0, bl1);
                mma_tf32(acc[nt], al[0], al[1], al[2], al[3], bh0, bh1);
            }
        }
        // in-place write back to Dp (warp-own rows; all A reads complete)
        float dgA = DG[m0 + gid], dgB = DG[m0 + gid + 8];
#pragma unroll
        for (int nt = 0; nt < 8; nt++) {
            int c = nt * 8 + tig * 2;
            Dp[(m0 + gid) * TS + c]     = acc[nt].x + dgA * V[c];
            Dp[(m0 + gid) * TS + c + 1] = acc[nt].y + dgA * V[c + 1];
            Dp[(m0 + gid + 8) * TS + c]     = acc[nt].z + dgB * V[c];
            Dp[(m0 + gid + 8) * TS + c + 1] = acc[nt].w + dgB * V[c + 1];
        }
    }
    __syncthreads();   // all W (W2d) reads done before overwrite below

    // LN dep (warp-own rows); concurrently stage W2r + load S_rev
#pragma unroll
    for (int t = 0; t < 16; t++) {
        int row = wid * 16 + t;
        float h0 = Dp[row * TS + lane];
        float h1 = Dp[row * TS + 32 + lane];
        float m = warp_sum(h0 + h1) * (1.f / 64.f);
        float e0 = h0 - m, e1 = h1 - m;
        float v = warp_sum(e0 * e0 + e1 * e1) * (1.f / 64.f);
        float inv = rsqrtf(v + 1e-5f);
        Dp[row * TS + lane]      = leaky(e0 * inv * V[128 + lane] + V[192 + lane]);
        Dp[row * TS + 32 + lane] = leaky(e1 * inv * V[160 + lane] + V[224 + lane]);
    }
    for (int i = tid; i < 4096; i += 256) W[(i >> 6) * 72 + (i & 63)] = revW2[i];
#pragma unroll
    for (int it = 0; it < 8; it++) {
        int fi = tid + it * 256;
        int r = fi >> 4, c4 = (fi & 15) * 4;
        float4 v = make_float4(0.f, 0.f, 0.f, 0.f);
        int row = row0 + r;
        if (row < n) v = *reinterpret_cast<const float4*>(&g_Srev[row * 64 + c4]);
        *reinterpret_cast<float4*>(&Rv[r * TS + c4]) = v;
    }
    __syncthreads();

    // ============ stage 2: rev (in-place in Rv) ============
    {
        float4 acc[8];
#pragma unroll
        for (int nt = 0; nt < 8; nt++) acc[nt] = make_float4(0.f, 0.f, 0.f, 0.f);
#pragma unroll
        for (int ks = 0; ks < 8; ks++) {
            int kb = ks * 8;
            uint32 ah[4], al[4];
            split_tf32(Rv[(m0 + gid) * TS + kb + tig],     ah[0], al[0]);
            split_tf32(Rv[(m0 + gid + 8) * TS + kb + tig], ah[1], al[1]);
            split_tf32(Rv[(m0 + gid) * TS + kb + tig + 4],     ah[2], al[2]);
            split_tf32(Rv[(m0 + gid + 8) * TS + kb + tig + 4], ah[3], al[3]);
#pragma unroll
            for (int nt = 0; nt < 8; nt++) {
                int nc = nt * 8 + gid;
                uint32 bh0, bl0, bh1, bl1;
                split_tf32(W[(kb + tig) * 72 + nc],     bh0, bl0);
                split_tf32(W[(kb + tig + 4) * 72 + nc], bh1, bl1);
                mma_tf32(acc[nt], ah[0], ah[1], ah[2], ah[3], bh0, bh1);
                mma_tf32(acc[nt], ah[0], ah[1], ah[2], ah[3], bl0, bl1);
                mma_tf32(acc[nt], al[0], al[1], al[2], al[3], bh0, bh1);
            }
        }
        float dgA = DG[128 + m0 + gid], dgB = DG[128 + m0 + gid + 8];
#pragma unroll
        for (int nt = 0; nt < 8; nt++) {
            int c = nt * 8 + tig * 2;
            Rv[(m0 + gid) * TS + c]     = acc[nt].x + dgA * V[64 + c];
            Rv[(m0 + gid) * TS + c + 1] = acc[nt].y + dgA * V[64 + c + 1];
            Rv[(m0 + gid + 8) * TS + c]     = acc[nt].z + dgB * V[64 + c];
            Rv[(m0 + gid + 8) * TS + c + 1] = acc[nt].w + dgB * V[64 + c + 1];
        }
    }
    __syncthreads();   // all W (W2r) reads done

    // LN rev; concurrently stage P[0:64] (for the Dp half of proj)
#pragma unroll
    for (int t = 0; t < 16; t++) {
        int row = wid * 16 + t;
        float h0 = Rv[row * TS + lane];
        float h1 = Rv[row * TS + 32 + lane];
        float m = warp_sum(h0 + h1) * (1.f / 64.f);
        float e0 = h0 - m, e1 = h1 - m;
        float v = warp_sum(e0 * e0 + e1 * e1) * (1.f / 64.f);
        float inv = rsqrtf(v + 1e-5f);
        Rv[row * TS + lane]      = leaky(e0 * inv * V[256 + lane] + V[320 + lane]);
        Rv[row * TS + 32 + lane] = leaky(e1 * inv * V[288 + lane] + V[352 + lane]);
    }
    for (int i = tid; i < 4096; i += 256) W[(i >> 6) * 72 + (i & 63)] = projW[i];
    __syncthreads();

    // ============ stage 3: proj (two passes over P) + reduce ============
    float4 acc[8];
#pragma unroll
    for (int nt = 0; nt < 8; nt++) acc[nt] = make_float4(0.f, 0.f, 0.f, 0.f);
#pragma unroll
    for (int ks = 0; ks < 8; ks++) {
        int kb = ks * 8;
        uint32 ah[4], al[4];
        split_tf32(Dp[(m0 + gid) * TS + kb + tig],     ah[0], al[0]);
        split_tf32(Dp[(m0 + gid + 8) * TS + kb + tig], ah[1], al[1]);
        split_tf32(Dp[(m0 + gid) * TS + kb + tig + 4],     ah[2], al[2]);
        split_tf32(Dp[(m0 + gid + 8) * TS + kb + tig + 4], ah[3], al[3]);
#pragma unroll
        for (int nt = 0; nt < 8; nt++) {
            int nc = nt * 8 + gid;
            uint32 bh0, bl0, bh1, bl1;
            split_tf32(W[(kb + tig) * 72 + nc],     bh0, bl0);
            split_tf32(W[(kb + tig + 4) * 72 + nc], bh1, bl1);
            mma_tf32(acc[nt], ah[0], ah[1], ah[2], ah[3], bh0, bh1);
            mma_tf32(acc[nt], ah[0], ah[1], ah[2], ah[3], bl0, bl1);
            mma_tf32(acc[nt], al[0], al[1], al[2], al[3], bh0, bh1);
        }
    }
    __syncthreads();   // all P[0:64] reads done
    for (int i = tid; i < 4096; i += 256) W[(i >> 6) * 72 + (i & 63)] = projW[4096 + i];
    __syncthreads();
#pragma unroll
    for (int ks = 0; ks < 8; ks++) {
        int kb = ks * 8;
        uint32 ah[4], al[4];
        split_tf32(Rv[(m0 + gid) * TS + kb + tig],     ah[0], al[0]);
        split_tf32(Rv[(m0 + gid + 8) * TS + kb + tig], ah[1], al[1]);
        split_tf32(Rv[(m0 + gid) * TS + kb + tig + 4],     ah[2], al[2]);
        split_tf32(Rv[(m0 + gid + 8) * TS + kb + tig + 4], ah[3], al[3]);
#pragma unroll
        for (int nt = 0; nt < 8; nt++) {
            int nc = nt * 8 + gid;
            uint32 bh0, bl0, bh1, bl1;
            split_tf32(W[(kb + tig) * 72 + nc],     bh0, bl0);
            split_tf32(W[(kb + tig + 4) * 72 + nc], bh1, bl1);
            mma_tf32(acc[nt], ah[0], ah[1], ah[2], ah[3], bh0, bh1);
            mma_tf32(acc[nt], ah[0], ah[1], ah[2], ah[3], bl0, bl1);
            mma_tf32(acc[nt], al[0], al[1], al[2], al[3], bh0, bh1);
        }
    }
    {
        int rowA = row0 + m0 + gid;
        int rowB = rowA + 8;
#pragma unroll
        for (int nt = 0; nt < 8; nt++) {
            int c = nt * 8 + tig * 2;
            float t0 = leaky(acc[nt].x + V[384 + c]);
            float t1 = leaky(acc[nt].y + V[384 + c + 1]);
            float t2 = leaky(acc[nt].z + V[384 + c]);
            float t3 = leaky(acc[nt].w + V[384 + c + 1]);
            float sx = ((rowA < n) ? t0 : 0.f) + ((rowB < n) ? t2 : 0.f);
            float sy = ((rowA < n) ? t1 : 0.f) + ((rowB < n) ? t3 : 0.f);
            sx += __shfl_xor_sync(FULL, sx, 4);
            sy += __shfl_xor_sync(FULL, sy, 4);
            sx += __shfl_xor_sync(FULL, sx, 8);
            sy += __shfl_xor_sync(FULL, sy, 8);
            sx += __shfl_xor_sync(FULL, sx, 16);
            sy += __shfl_xor_sync(FULL, sy, 16);
            if (gid == 0) {
                CP[wid * 64 + c]     = sx;
                CP[wid * 64 + c + 1] = sy;
            }
            if (rowA == 0) {
                out[64 + c]     = t0;
                out[64 + c + 1] = t1;
            }
        }
    }
    __syncthreads();
    if (tid < 64) {
        float s = 0.f;
#pragma unroll
        for (int g = 0; g < 8; g++) s += CP[g * 64 + tid];
        atomicAdd(&g_colsum[tid], s);
    }
}

// ---------------------------------------------------------------------------
// K6: finalize
// ---------------------------------------------------------------------------
__global__ void k_final(const int* __restrict__ counts,
                        const float* __restrict__ devx,
                        const float* __restrict__ timex,
                        const float* __restrict__ devW,
                        const float* __restrict__ devb,
                        float* __restrict__ out) {
    int tid = threadIdx.x;
    if (tid < 64) {
        int c = counts[0];
        if (c < 1) c = 1;
        out[tid] = g_colsum[tid] / (float)c;
    } else if (tid < 128) {
        int j = tid - 64;
        float p = devb[j];
#pragma unroll 8
        for (int k = 0; k < 96; k++) p += devx[k] * devW[k * 64 + j];
        p += (timex[0] * 1e-5f) * devW[96 * 64 + j];
        out[128 + j] = leaky(p);
    }
}

// ---------------------------------------------------------------------------
// Launch. k_gemm_tc stays at slot 4 (the ncu-profiled launch).
// ---------------------------------------------------------------------------
extern "C" void kernel_launch(void* const* d_in, const int* in_sizes, int n_in,
                              void* d_out, int out_size) {
    const float* data_x    = (const float*)d_in[0];
    const float* tasks_x   = (const float*)d_in[1];
    const float* devices_x = (const float*)d_in[2];
    const float* time_x    = (const float*)d_in[3];
    const int*   dt_src    = (const int*)d_in[4];
    const int*   dt_dst    = (const int*)d_in[5];
    const int*   tt_src    = (const int*)d_in[6];
    const int*   tt_dst    = (const int*)d_in[7];
    const int*   counts    = (const int*)d_in[8];
    const float* gcWrel    = (const float*)d_in[9];
    const float* gcbrel    = (const float*)d_in[10];
    const float* gcWroot   = (const float*)d_in[11];
    const float* gclng     = (const float*)d_in[12];
    const float* gclnb     = (const float*)d_in[13];
    const float* depW1     = (const float*)d_in[14];
    const float* depb1     = (const float*)d_in[15];
    const float* depW2     = (const float*)d_in[16];
    const float* depb2     = (const float*)d_in[17];
    const float* deplng    = (const float*)d_in[18];
    const float* deplnb    = (const float*)d_in[19];
    const float* revW1     = (const float*)d_in[20];
    const float* revb1     = (const float*)d_in[21];
    const float* revW2     = (const float*)d_in[22];
    const float* revb2     = (const float*)d_in[23];
    const float* revlng    = (const float*)d_in[24];
    const float* revlnb    = (const float*)d_in[25];
    const float* devW      = (const float*)d_in[26];
    const float* devb      = (const float*)d_in[27];
    const float* projW     = (const float*)d_in[28];
    const float* projb     = (const float*)d_in[29];
    float* out = (float*)d_out;

    int n    = in_sizes[1] / 12;
    int e_dt = in_sizes[4];
    int e_tt = in_sizes[6];
    int nblk = (n + 1023) / 1024;
    int emax = e_dt > e_tt ? e_dt : e_tt;

    cudaFuncSetAttribute(k_gemm_tc, cudaFuncAttributeMaxDynamicSharedMemorySize, 69632);
    cudaFuncSetAttribute(k_tail2,   cudaFuncAttributeMaxDynamicSharedMemorySize, 92928);

    int gb = (n + 127) / 128;

    k_zero<<<(n * 8 + 255) / 256, 256>>>(n);                                     // 1
    k_edges_pre<<<(emax + 255) / 256, 256>>>(data_x, dt_src, dt_dst, e_dt,
                                             tt_src, tt_dst, e_tt);              // 2
    k_fused<<<(n * 32 + 255) / 256, 256>>>(tasks_x, gcWrel, gcbrel, gcWroot,
                                           gclng, gclnb, n);                     // 3
    dim3 gg(gb, 2);
    k_gemm_tc<<<gg, 256, 69632>>>(depW1, revW1, n);                              // 4 <- profiled

    dim3 sg(nblk, 2);
    k_scan_blk<<<sg, 256>>>(n);                                                  // 5
    k_scan_top<<<1, 64>>>(nblk);                                                 // 6
    k_scan_fix<<<sg, 256>>>(n, e_tt);                                            // 7
    k_scatter<<<(e_tt + 255) / 256, 256>>>(tt_src, tt_dst, e_tt);                // 8

    dim3 ag((n + 7) / 8, 2);
    k_agg<<<ag, 256>>>(depb1, revb1, n);                                         // 9

    k_tail2<<<gb, 256, 92928>>>(depW2, depb2, deplng, deplnb,
                                revW2, revb2, revlng, revlnb,
                                projW, projb, out, n);                           // 10
    k_final<<<1, 128>>>(counts, devices_x, time_x, devW, devb, out);             // 11
}

// round 15
// speedup vs baseline: 2.1557x; 1.1080x over previous
#include <cuda_runtime.h>

#define NT_MAX 200000
#define ETT_MAX 1100000

typedef unsigned int uint32;

// ---------------------------------------------------------------------------
// Scratch (__device__ globals — allocation-free rule)
// ---------------------------------------------------------------------------
__device__ float g_agg  [NT_MAX * 8];   // padded row stride 8 for v4 red atomics
__device__ float g_fused[NT_MAX * 64];
__device__ float g_Bdep [NT_MAX * 64];
__device__ float g_Cdep [NT_MAX * 64];
__device__ float g_Brev [NT_MAX * 64];
__device__ float g_Crev [NT_MAX * 64];
__device__ float g_Sdep [NT_MAX * 64];
__device__ float g_Srev [NT_MAX * 64];
__device__ int   g_degD [NT_MAX];
__device__ int   g_degR [NT_MAX];
__device__ int   g_ptrD [NT_MAX + 1];
__device__ int   g_ptrR [NT_MAX + 1];
__device__ int   g_curD [NT_MAX];
__device__ int   g_curR [NT_MAX];
__device__ int   g_srcD [ETT_MAX];
__device__ int   g_srcR [ETT_MAX];
__device__ int   g_bsumD[512];
__device__ int   g_bsumR[512];
__device__ float g_colsum[64];

__device__ __forceinline__ float leaky(float x) { return x > 0.f ? x : 0.01f * x; }

__device__ __forceinline__ float warp_sum(float v) {
#pragma unroll
    for (int o = 16; o > 0; o >>= 1) v += __shfl_xor_sync(0xffffffffu, v, o);
    return v;
}

// ---- tf32 helpers ---------------------------------------------------------
__device__ __forceinline__ uint32 tf32_of(float x) {
    uint32 u;
    asm("cvt.rna.tf32.f32 %0, %1;" : "=r"(u) : "f"(x));
    return u;
}
__device__ __forceinline__ void split_tf32(float x, uint32& hi, uint32& lo) {
    hi = tf32_of(x);
    lo = tf32_of(x - __uint_as_float(hi));
}
__device__ __forceinline__ void mma_tf32(float4& d,
                                         uint32 a0, uint32 a1, uint32 a2, uint32 a3,
                                         uint32 b0, uint32 b1) {
    asm("mma.sync.aligned.m16n8k8.row.col.f32.tf32.tf32.f32 "
        "{%0,%1,%2,%3},{%4,%5,%6,%7},{%8,%9},{%0,%1,%2,%3};"
        : "+f"(d.x), "+f"(d.y), "+f"(d.z), "+f"(d.w)
        : "r"(a0), "r"(a1), "r"(a2), "r"(a3), "r"(b0), "r"(b1));
}

// ---------------------------------------------------------------------------
// K0: zero accumulators
// ---------------------------------------------------------------------------
__global__ void k_zero(int n) {
    int i = blockIdx.x * blockDim.x + threadIdx.x;
    if (i < n * 8) g_agg[i] = 0.f;
    if (i < n) { g_degD[i] = 0; g_degR[i] = 0; }
    if (i < 64) g_colsum[i] = 0.f;
}

// ---------------------------------------------------------------------------
// K1: data->task scatter-add (v4 red) + tt degree histograms (fused)
// ---------------------------------------------------------------------------
__global__ void k_edges_pre(const float* __restrict__ data_x,
                            const int* __restrict__ dsrc, const int* __restrict__ ddst,
                            int e_dt,
                            const int* __restrict__ tsrc, const int* __restrict__ tdst,
                            int e_tt) {
    int e = blockIdx.x * blockDim.x + threadIdx.x;
    if (e < e_dt) {
        int s = __ldg(&dsrc[e]);
        int d = __ldg(&ddst[e]);
        const float* xr = data_x + s * 5;
        float x0 = __ldg(&xr[0]), x1 = __ldg(&xr[1]), x2 = __ldg(&xr[2]);
        float x3 = __ldg(&xr[3]), x4 = __ldg(&xr[4]);
        float* ar = g_agg + d * 8;
        asm volatile("red.global.add.v4.f32 [%0], {%1,%2,%3,%4};"
                     :: "l"(ar), "f"(x0), "f"(x1), "f"(x2), "f"(x3) : "memory");
        atomicAdd(ar + 4, x4);
    }
    if (e < e_tt) {
        atomicAdd(&g_degD[__ldg(&tdst[e])], 1);
        atomicAdd(&g_degR[__ldg(&tsrc[e])], 1);
    }
}

// ---------------------------------------------------------------------------
// Scan stage 1
// ---------------------------------------------------------------------------
__global__ __launch_bounds__(256) void k_scan_blk(int n) {
    int arr = blockIdx.y;
    const int* deg = arr ? g_degR : g_degD;
    int* ptr = arr ? g_ptrR : g_ptrD;
    int* bsum = arr ? g_bsumR : g_bsumD;
    __shared__ int sh[256];
    int tid = threadIdx.x;
    int base = blockIdx.x * 1024;
    int v[4]; int s = 0;
#pragma unroll
    for (int j = 0; j < 4; j++) {
        int idx = base + tid * 4 + j;
        v[j] = (idx < n) ? deg[idx] : 0;
        s += v[j];
    }
    sh[tid] = s;
    __syncthreads();
#pragma unroll
    for (int d = 1; d < 256; d <<= 1) {
        int t = 0;
        if (tid >= d) t = sh[tid - d];
        __syncthreads();
        sh[tid] += t;
        __syncthreads();
    }
    int off = sh[tid] - s;
#pragma unroll
    for (int j = 0; j < 4; j++) {
        int idx = base + tid * 4 + j;
        if (idx < n) ptr[idx] = off;
        off += v[j];
    }
    if (tid == 0) bsum[blockIdx.x] = sh[255];
}

// ---------------------------------------------------------------------------
// Scan stage 2: warp-parallel scan of block sums (one warp per array)
// ---------------------------------------------------------------------------
__global__ void k_scan_top(int nblk) {
    int lane = threadIdx.x & 31;
    int* bs = (threadIdx.x < 32) ? g_bsumD : g_bsumR;
    int base = 0;
    for (int i0 = 0; i0 < nblk; i0 += 32) {
        int idx = i0 + lane;
        int v = (idx < nblk) ? bs[idx] : 0;
        int incl = v;
#pragma unroll
        for (int o = 1; o < 32; o <<= 1) {
            int t = __shfl_up_sync(0xffffffffu, incl, o);
            if (lane >= o) incl += t;
        }
        if (idx < nblk) bs[idx] = base + incl - v;
        base += __shfl_sync(0xffffffffu, incl, 31);
    }
}

// ---------------------------------------------------------------------------
// Scan stage 3
// ---------------------------------------------------------------------------
__global__ __launch_bounds__(256) void k_scan_fix(int n, int E) {
    int arr = blockIdx.y;
    int* ptr = arr ? g_ptrR : g_ptrD;
    int* cur = arr ? g_curR : g_curD;
    const int* bsum = arr ? g_bsumR : g_bsumD;
    int off = bsum[blockIdx.x];
    int base = blockIdx.x * 1024 + threadIdx.x * 4;
#pragma unroll
    for (int j = 0; j < 4; j++) {
        int idx = base + j;
        if (idx < n) { int v = ptr[idx] + off; ptr[idx] = v; cur[idx] = v; }
    }
    if (blockIdx.x == 0 && threadIdx.x == 0) ptr[n] = E;
}

// ---------------------------------------------------------------------------
// K1c: scatter edges into CSR
// ---------------------------------------------------------------------------
__global__ void k_scatter(const int* __restrict__ tsrc, const int* __restrict__ tdst, int E) {
    int e = blockIdx.x * blockDim.x + threadIdx.x;
    if (e >= E) return;
    int s = __ldg(&tsrc[e]);
    int d = __ldg(&tdst[e]);
    int p = atomicAdd(&g_curD[d], 1);
    g_srcD[p] = s;
    int q = atomicAdd(&g_curR[s], 1);
    g_srcR[q] = d;
}

// ---------------------------------------------------------------------------
// K2: fused = leaky(LN(agg @ Wrel + brel + tasks @ Wroot))   (warp per row)
// ---------------------------------------------------------------------------
__global__ void k_fused(const float* __restrict__ tasks_x,
                        const float* __restrict__ Wrel, const float* __restrict__ brel,
                        const float* __restrict__ Wroot,
                        const float* __restrict__ lng, const float* __restrict__ lnb,
                        int n) {
    int gt = blockIdx.x * blockDim.x + threadIdx.x;
    int r = gt >> 5, lane = gt & 31;
    if (r >= n) return;
    float p0 = __ldg(&brel[lane]);
    float p1 = __ldg(&brel[lane + 32]);
    const float* ar = g_agg + r * 8;
#pragma unroll
    for (int k = 0; k < 5; k++) {
        float a = ar[k];
        p0 += a * __ldg(&Wrel[k * 64 + lane]);
        p1 += a * __ldg(&Wrel[k * 64 + lane + 32]);
    }
    const float* tr = tasks_x + r * 12;
#pragma unroll
    for (int k = 0; k < 12; k++) {
        float t = __ldg(&tr[k]);
        p0 += t * __ldg(&Wroot[k * 64 + lane]);
        p1 += t * __ldg(&Wroot[k * 64 + lane + 32]);
    }
    float m = warp_sum(p0 + p1) * (1.f / 64.f);
    float d0 = p0 - m, d1 = p1 - m;
    float v = warp_sum(d0 * d0 + d1 * d1) * (1.f / 64.f);
    float inv = rsqrtf(v + 1e-5f);
    float y0 = leaky(d0 * inv * __ldg(&lng[lane])      + __ldg(&lnb[lane]));
    float y1 = leaky(d1 * inv * __ldg(&lng[lane + 32]) + __ldg(&lnb[lane + 32]));
    g_fused[r * 64 + lane]      = y0;
    g_fused[r * 64 + lane + 32] = y1;
}

// ---------------------------------------------------------------------------
// K3: tensor-core B/C GEMM (3xTF32), ONE conv per block (blockIdx.y).
// W pre-split into smem hi/lo planes per half -> mainloop W reads are pure LDS.
// Block = 128 rows, 256 threads, warp = 16 rows x 64 cols.
// smem floats: Xs [128][68]=8704 | Whi [64][72]=4608 | Wlo 4608  (71680 B, 3/SM)
// ---------------------------------------------------------------------------
__global__ __launch_bounds__(256, 3) void k_gemm_tc(
    const float* __restrict__ depW1, const float* __restrict__ revW1, int n) {
    extern __shared__ float sm[];
    float* Xs  = sm;            // [128][68]
    float* Whi = sm + 8704;     // [64][72]
    float* Wlo = sm + 13312;    // [64][72]
    int tid = threadIdx.x;
    int row0 = blockIdx.x * 128;
    int conv = blockIdx.y;
    const float* W1 = conv ? revW1 : depW1;

#pragma unroll
    for (int it = 0; it < 8; it++) {
        int fi = tid + it * 256;
        int r = fi >> 4, c4 = (fi & 15) * 4;
        float4 v = make_float4(0.f, 0.f, 0.f, 0.f);
        int row = row0 + r;
        if (row < n) v = *reinterpret_cast<const float4*>(&g_fused[row * 64 + c4]);
        *reinterpret_cast<float4*>(&Xs[r * 68 + c4]) = v;
    }

    int lane = tid & 31, wid = tid >> 5;
    int gid = lane >> 2, tig = lane & 3;
    int m0 = wid * 16;

#pragma unroll 1
    for (int half = 0; half < 2; half++) {
        // stage + split W for this half: half 0 -> W1b, half 1 -> W1a - W1b
        for (int i = tid; i < 4096; i += 256) {
            int k = i >> 6, j = i & 63;
            float wB = W1[(64 + k) * 64 + j];
            float w = (half == 0) ? wB : (W1[k * 64 + j] - wB);
            uint32 hi, lo;
            split_tf32(w, hi, lo);
            Whi[k * 72 + j] = __uint_as_float(hi);
            Wlo[k * 72 + j] = __uint_as_float(lo);
        }
        __syncthreads();

        float4 acc[8];
#pragma unroll
        for (int nt = 0; nt < 8; nt++) acc[nt] = make_float4(0.f, 0.f, 0.f, 0.f);
#pragma unroll
        for (int ks = 0; ks < 8; ks++) {
            int kb = ks * 8;
            uint32 ah[4], al[4];
            split_tf32(Xs[(m0 + gid) * 68 + kb + tig],     ah[0], al[0]);
            split_tf32(Xs[(m0 + gid + 8) * 68 + kb + tig], ah[1], al[1]);
            split_tf32(Xs[(m0 + gid) * 68 + kb + tig + 4],     ah[2], al[2]);
            split_tf32(Xs[(m0 + gid + 8) * 68 + kb + tig + 4], ah[3], al[3]);
#pragma unroll
            for (int nt = 0; nt < 8; nt++) {
                int nc = nt * 8 + gid;
                uint32 bh0 = __float_as_uint(Whi[(kb + tig) * 72 + nc]);
                uint32 bh1 = __float_as_uint(Whi[(kb + tig + 4) * 72 + nc]);
                uint32 bl0 = __float_as_uint(Wlo[(kb + tig) * 72 + nc]);
                uint32 bl1 = __float_as_uint(Wlo[(kb + tig + 4) * 72 + nc]);
                mma_tf32(acc[nt], ah[0], ah[1], ah[2], ah[3], bh0, bh1);
                mma_tf32(acc[nt], ah[0], ah[1], ah[2], ah[3], bl0, bl1);
                mma_tf32(acc[nt], al[0], al[1], al[2], al[3], bh0, bh1);
            }
        }
        float* O = (half == 0) ? (conv ? g_Brev : g_Bdep) : (conv ? g_Crev : g_Cdep);
        int rowA = row0 + m0 + gid;
        int rowB = rowA + 8;
#pragma unroll
        for (int nt = 0; nt < 8; nt++) {
            int c = nt * 8 + tig * 2;
            if (rowA < n)
                *reinterpret_cast<float2*>(&O[rowA * 64 + c]) =
                    make_float2(acc[nt].x, acc[nt].y);
            if (rowB < n)
                *reinterpret_cast<float2*>(&O[rowB * 64 + c]) =
                    make_float2(acc[nt].z, acc[nt].w);
        }
        __syncthreads();   // W reads done before next-half restage
    }
}

// ---------------------------------------------------------------------------
// K4: edge aggregation, both convs in one launch (blockIdx.y = conv).
// ---------------------------------------------------------------------------
__global__ __launch_bounds__(256) void k_agg(const float* __restrict__ depb1,
                                             const float* __restrict__ revb1,
                                             int n) {
    int conv = blockIdx.y;
    const int* ptr  = conv ? g_ptrR : g_ptrD;
    const int* srcA = conv ? g_srcR : g_srcD;
    const float* B  = conv ? g_Brev : g_Bdep;
    const float* C  = conv ? g_Crev : g_Cdep;
    const float* b1 = conv ? revb1 : depb1;
    float* S        = conv ? g_Srev : g_Sdep;
    const unsigned FULL = 0xffffffffu;
    int lane = threadIdx.x & 31, wid = threadIdx.x >> 5;
    int r = blockIdx.x * 8 + wid;
    if (r >= n) return;
    int a0 = ptr[r], a1 = ptr[r + 1];
    float2 cv = *reinterpret_cast<const float2*>(&C[r * 64 + 2 * lane]);
    float c0 = cv.x + __ldg(&b1[2 * lane]);
    float c1 = cv.y + __ldg(&b1[2 * lane + 1]);
    float s0 = 0.f, s1 = 0.f;
    for (int i0 = a0; i0 < a1; i0 += 32) {
        int cnt = min(32, a1 - i0);
        int mi = (lane < cnt) ? srcA[i0 + lane] : 0;
        int j = 0;
        for (; j + 4 <= cnt; j += 4) {
            int x0 = __shfl_sync(FULL, mi, j);
            int x1 = __shfl_sync(FULL, mi, j + 1);
            int x2 = __shfl_sync(FULL, mi, j + 2);
            int x3 = __shfl_sync(FULL, mi, j + 3);
            float2 b0 = *reinterpret_cast<const float2*>(&B[x0 * 64 + 2 * lane]);
            float2 b1v = *reinterpret_cast<const float2*>(&B[x1 * 64 + 2 * lane]);
            float2 b2 = *reinterpret_cast<const float2*>(&B[x2 * 64 + 2 * lane]);
            float2 b3 = *reinterpret_cast<const float2*>(&B[x3 * 64 + 2 * lane]);
            s0 += leaky(c0 + b0.x) + leaky(c0 + b1v.x) + leaky(c0 + b2.x) + leaky(c0 + b3.x);
            s1 += leaky(c1 + b0.y) + leaky(c1 + b1v.y) + leaky(c1 + b2.y) + leaky(c1 + b3.y);
        }
        for (; j < cnt; j++) {
            int xs = __shfl_sync(FULL, mi, j);
            float2 b = *reinterpret_cast<const float2*>(&B[xs * 64 + 2 * lane]);
            s0 += leaky(c0 + b.x);
            s1 += leaky(c1 + b.y);
        }
    }
    *reinterpret_cast<float2*>(&S[r * 64 + 2 * lane]) = make_float2(s0, s1);
}

// ---------------------------------------------------------------------------
// K5: tiled tail, TC GEMMs. W pre-split into smem hi/lo at stage time.
// In-place S->H per warp. projW consumed in two halves.
// smem floats: Whi 4608 | Wlo 4608 | Dp 8704 | Rv 8704 | V 448 | CP 512 | DG 256
//   = 27840 floats = 111360 B -> 2 blocks/SM
// ---------------------------------------------------------------------------
#define TS 68

__global__ __launch_bounds__(256, 2) void k_tail2(
    const float* __restrict__ depW2, const float* __restrict__ depb2,
    const float* __restrict__ depg,  const float* __restrict__ depb,
    const float* __restrict__ revW2, const float* __restrict__ revb2,
    const float* __restrict__ revg,  const float* __restrict__ revb,
    const float* __restrict__ projW, const float* __restrict__ projb,
    float* __restrict__ out, int n) {
    extern __shared__ float sm[];
    float* Whi = sm;            // [64][72]
    float* Wlo = sm + 4608;     // [64][72]
    float* Dp  = sm + 9216;     // [128][68]
    float* Rv  = sm + 17920;    // [128][68]
    float* V   = sm + 26624;    // 448
    float* CP  = sm + 27072;    // 512
    float* DG  = sm + 27584;    // 256

    int tid = threadIdx.x;
    int row0 = blockIdx.x * 128;
    int lane = tid & 31, wid = tid >> 5;
    int gid = lane >> 2, tig = lane & 3;
    int m0 = wid * 16;
    const unsigned FULL = 0xffffffffu;

    if (tid < 64) {
        V[tid]       = depb2[tid];
        V[64 + tid]  = revb2[tid];
        V[128 + tid] = depg[tid];
        V[192 + tid] = depb[tid];
        V[256 + tid] = revg[tid];
        V[320 + tid] = revb[tid];
        V[384 + tid] = projb[tid];
    }
    if (tid < 128) {
        int row = row0 + tid;
        DG[tid]       = (row < n) ? (float)(g_ptrD[row + 1] - g_ptrD[row]) : 0.f;
        DG[128 + tid] = (row < n) ? (float)(g_ptrR[row + 1] - g_ptrR[row]) : 0.f;
    }

    // ============ stage 1: dep ============
    for (int i = tid; i < 4096; i += 256) {
        uint32 hi, lo;
        split_tf32(depW2[i], hi, lo);
        Whi[(i >> 6) * 72 + (i & 63)] = __uint_as_float(hi);
        Wlo[(i >> 6) * 72 + (i & 63)] = __uint_as_float(lo);
    }
#pragma unroll
    for (int it = 0; it < 8; it++) {
        int fi = tid + it * 256;
        int r = fi >> 4, c4 = (fi & 15) * 4;
        float4 v = make_float4(0.f, 0.f, 0.f, 0.f);
        int row = row0 + r;
        if (row < n) v = *reinterpret_cast<const float4*>(&g_Sdep[row * 64 + c4]);
        *reinterpret_cast<float4*>(&Dp[r * TS + c4]) = v;
    }
    __syncthreads();

    {
        float4 acc[8];
#pragma unroll
        for (int nt = 0; nt < 8; nt++) acc[nt] = make_float4(0.f, 0.f, 0.f, 0.f);
#pragma unroll
        for (int ks = 0; ks < 8; ks++) {
            int kb = ks * 8;
            uint32 ah[4], al[4];
            split_tf32(Dp[(m0 + gid) * TS + kb + tig],     ah[0], al[0]);
            split_tf32(Dp[(m0 + gid + 8) * TS + kb + tig], ah[1], al[1]);
            split_tf32(Dp[(m0 + gid) * TS + kb + tig + 4],     ah[2], al[2]);
            split_tf32(Dp[(m0 + gid + 8) * TS + kb + tig + 4], ah[3], al[3]);
#pragma unroll
            for (int nt = 0; nt < 8; nt++) {
                int nc = nt * 8 + gid;
                uint32 bh0 = __float_as_uint(Whi[(kb + tig) * 72 + nc]);
                uint32 bh1 = __float_as_uint(Whi[(kb + tig + 4) * 72 + nc]);
                uint32 bl0 = __float_as_uint(Wlo[(kb + tig) * 72 + nc]);
                uint32 bl1 = __float_as_uint(Wlo[(kb + tig + 4) * 72 + nc]);
                mma_tf32(acc[nt], ah[0], ah[1], ah[2], ah[3], bh0, bh1);
                mma_tf32(acc[nt], ah[0], ah[1], ah[2], ah[3], bl0, bl1);
                mma_tf32(acc[nt], al[0], al[1], al[2], al[3], bh0, bh1);
            }
        }
        // in-place write back (warp-own rows; all A reads complete)
        float dgA = DG[m0 + gid], dgB = DG[m0 + gid + 8];
#pragma unroll
        for (int nt = 0; nt < 8; nt++) {
            int c = nt * 8 + tig * 2;
            Dp[(m0 + gid) * TS + c]     = acc[nt].x + dgA * V[c];
            Dp[(m0 + gid) * TS + c + 1] = acc[nt].y + dgA * V[c + 1];
            Dp[(m0 + gid + 8) * TS + c]     = acc[nt].z + dgB * V[c];
            Dp[(m0 + gid + 8) * TS + c + 1] = acc[nt].w + dgB * V[c + 1];
        }
    }
    __syncthreads();   // all W2d reads done before restage

    // LN dep (warp-own rows); concurrently stage W2r + load S_rev
#pragma unroll
    for (int t = 0; t < 16; t++) {
        int row = wid * 16 + t;
        float h0 = Dp[row * TS + lane];
        float h1 = Dp[row * TS + 32 + lane];
        float m = warp_sum(h0 + h1) * (1.f / 64.f);
        float e0 = h0 - m, e1 = h1 - m;
        float v = warp_sum(e0 * e0 + e1 * e1) * (1.f / 64.f);
        float inv = rsqrtf(v + 1e-5f);
        Dp[row * TS + lane]      = leaky(e0 * inv * V[128 + lane] + V[192 + lane]);
        Dp[row * TS + 32 + lane] = leaky(e1 * inv * V[160 + lane] + V[224 + lane]);
    }
    for (int i = tid; i < 4096; i += 256) {
        uint32 hi, lo;
        split_tf32(revW2[i], hi, lo);
        Whi[(i >> 6) * 72 + (i & 63)] = __uint_as_float(hi);
        Wlo[(i >> 6) * 72 + (i & 63)] = __uint_as_float(lo);
    }
#pragma unroll
    for (int it = 0; it < 8; it++) {
        int fi = tid + it * 256;
        int r = fi >> 4, c4 = (fi & 15) * 4;
        float4 v = make_float4(0.f, 0.f, 0.f, 0.f);
        int row = row0 + r;
        if (row < n) v = *reinterpret_cast<const float4*>(&g_Srev[row * 64 + c4]);
        *reinterpret_cast<float4*>(&Rv[r * TS + c4]) = v;
    }
    __syncthreads();

    // ============ stage 2: rev (in-place in Rv) ============
    {
        float4 acc[8];
#pragma unroll
        for (int nt = 0; nt < 8; nt++) acc[nt] = make_float4(0.f, 0.f, 0.f, 0.f);
#pragma unroll
        for (int ks = 0; ks < 8; ks++) {
            int kb = ks * 8;
            uint32 ah[4], al[4];
            split_tf32(Rv[(m0 + gid) * TS + kb + tig],     ah[0], al[0]);
            split_tf32(Rv[(m0 + gid + 8) * TS + kb + tig], ah[1], al[1]);
            split_tf32(Rv[(m0 + gid) * TS + kb + tig + 4],     ah[2], al[2]);
            split_tf32(Rv[(m0 + gid + 8) * TS + kb + tig + 4], ah[3], al[3]);
#pragma unroll
            for (int nt = 0; nt < 8; nt++) {
                int nc = nt * 8 + gid;
                uint32 bh0 = __float_as_uint(Whi[(kb + tig) * 72 + nc]);
                uint32 bh1 = __float_as_uint(Whi[(kb + tig + 4) * 72 + nc]);
                uint32 bl0 = __float_as_uint(Wlo[(kb + tig) * 72 + nc]);
                uint32 bl1 = __float_as_uint(Wlo[(kb + tig + 4) * 72 + nc]);
                mma_tf32(acc[nt], ah[0], ah[1], ah[2], ah[3], bh0, bh1);
                mma_tf32(acc[nt], ah[0], ah[1], ah[2], ah[3], bl0, bl1);
                mma_tf32(acc[nt], al[0], al[1], al[2], al[3], bh0, bh1);
            }
        }
        float dgA = DG[128 + m0 + gid], dgB = DG[128 + m0 + gid + 8];
#pragma unroll
        for (int nt = 0; nt < 8; nt++) {
            int c = nt * 8 + tig * 2;
            Rv[(m0 + gid) * TS + c]     = acc[nt].x + dgA * V[64 + c];
            Rv[(m0 + gid) * TS + c + 1] = acc[nt].y + dgA * V[64 + c + 1];
            Rv[(m0 + gid + 8) * TS + c]     = acc[nt].z + dgB * V[64 + c];
            Rv[(m0 + gid + 8) * TS + c + 1] = acc[nt].w + dgB * V[64 + c + 1];
        }
    }
    __syncthreads();   // all W2r reads done

    // LN rev; concurrently stage P[0:64]
#pragma unroll
    for (int t = 0; t < 16; t++) {
        int row = wid * 16 + t;
        float h0 = Rv[row * TS + lane];
        float h1 = Rv[row * TS + 32 + lane];
        float m = warp_sum(h0 + h1) * (1.f / 64.f);
        float e0 = h0 - m, e1 = h1 - m;
        float v = warp_sum(e0 * e0 + e1 * e1) * (1.f / 64.f);
        float inv = rsqrtf(v + 1e-5f);
        Rv[row * TS + lane]      = leaky(e0 * inv * V[256 + lane] + V[320 + lane]);
        Rv[row * TS + 32 + lane] = leaky(e1 * inv * V[288 + lane] + V[352 + lane]);
    }
    for (int i = tid; i < 4096; i += 256) {
        uint32 hi, lo;
        split_tf32(projW[i], hi, lo);
        Whi[(i >> 6) * 72 + (i & 63)] = __uint_as_float(hi);
        Wlo[(i >> 6) * 72 + (i & 63)] = __uint_as_float(lo);
    }
    __syncthreads();

    // ============ stage 3: proj (two passes over P) + reduce ============
    float4 acc[8];
#pragma unroll
    for (int nt = 0; nt < 8; nt++) acc[nt] = make_float4(0.f, 0.f, 0.f, 0.f);
#pragma unroll
    for (int ks = 0; ks < 8; ks++) {
        int kb = ks * 8;
        uint32 ah[4], al[4];
        split_tf32(Dp[(m0 + gid) * TS + kb + tig],     ah[0], al[0]);
        split_tf32(Dp[(m0 + gid + 8) * TS + kb + tig], ah[1], al[1]);
        split_tf32(Dp[(m0 + gid) * TS + kb + tig + 4],     ah[2], al[2]);
        split_tf32(Dp[(m0 + gid + 8) * TS + kb + tig + 4], ah[3], al[3]);
#pragma unroll
        for (int nt = 0; nt < 8; nt++) {
            int nc = nt * 8 + gid;
            uint32 bh0 = __float_as_uint(Whi[(kb + tig) * 72 + nc]);
            uint32 bh1 = __float_as_uint(Whi[(kb + tig + 4) * 72 + nc]);
            uint32 bl0 = __float_as_uint(Wlo[(kb + tig) * 72 + nc]);
            uint32 bl1 = __float_as_uint(Wlo[(kb + tig + 4) * 72 + nc]);
            mma_tf32(acc[nt], ah[0], ah[1], ah[2], ah[3], bh0, bh1);
            mma_tf32(acc[nt], ah[0], ah[1], ah[2], ah[3], bl0, bl1);
            mma_tf32(acc[nt], al[0], al[1], al[2], al[3], bh0, bh1);
        }
    }
    __syncthreads();   // all P[0:64] reads done
    for (int i = tid; i < 4096; i += 256) {
        uint32 hi, lo;
        split_tf32(projW[4096 + i], hi, lo);
        Whi[(i >> 6) * 72 + (i & 63)] = __uint_as_float(hi);
        Wlo[(i >> 6) * 72 + (i & 63)] = __uint_as_float(lo);
    }
    __syncthreads();
#pragma unroll
    for (int ks = 0; ks < 8; ks++) {
        int kb = ks * 8;
        uint32 ah[4], al[4];
        split_tf32(Rv[(m0 + gid) * TS + kb + tig],     ah[0], al[0]);
        split_tf32(Rv[(m0 + gid + 8) * TS + kb + tig], ah[1], al[1]);
        split_tf32(Rv[(m0 + gid) * TS + kb + tig + 4],     ah[2], al[2]);
        split_tf32(Rv[(m0 + gid + 8) * TS + kb + tig + 4], ah[3], al[3]);
#pragma unroll
        for (int nt = 0; nt < 8; nt++) {
            int nc = nt * 8 + gid;
            uint32 bh0 = __float_as_uint(Whi[(kb + tig) * 72 + nc]);
            uint32 bh1 = __float_as_uint(Whi[(kb + tig + 4) * 72 + nc]);
            uint32 bl0 = __float_as_uint(Wlo[(kb + tig) * 72 + nc]);
            uint32 bl1 = __float_as_uint(Wlo[(kb + tig + 4) * 72 + nc]);
            mma_tf32(acc[nt], ah[0], ah[1], ah[2], ah[3], bh0, bh1);
            mma_tf32(acc[nt], ah[0], ah[1], ah[2], ah[3], bl0, bl1);
            mma_tf32(acc[nt], al[0], al[1], al[2], al[3], bh0, bh1);
        }
    }
    {
        int rowA = row0 + m0 + gid;
        int rowB = rowA + 8;
#pragma unroll
        for (int nt = 0; nt < 8; nt++) {
            int c = nt * 8 + tig * 2;
            float t0 = leaky(acc[nt].x + V[384 + c]);
            float t1 = leaky(acc[nt].y + V[384 + c + 1]);
            float t2 = leaky(acc[nt].z + V[384 + c]);
            float t3 = leaky(acc[nt].w + V[384 + c + 1]);
            float sx = ((rowA < n) ? t0 : 0.f) + ((rowB < n) ? t2 : 0.f);
            float sy = ((rowA < n) ? t1 : 0.f) + ((rowB < n) ? t3 : 0.f);
            sx += __shfl_xor_sync(FULL, sx, 4);
            sy += __shfl_xor_sync(FULL, sy, 4);
            sx += __shfl_xor_sync(FULL, sx, 8);
            sy += __shfl_xor_sync(FULL, sy, 8);
            sx += __shfl_xor_sync(FULL, sx, 16);
            sy += __shfl_xor_sync(FULL, sy, 16);
            if (gid == 0) {
                CP[wid * 64 + c]     = sx;
                CP[wid * 64 + c + 1] = sy;
            }
            if (rowA == 0) {
                out[64 + c]     = t0;
                out[64 + c + 1] = t1;
            }
        }
    }
    __syncthreads();
    if (tid < 64) {
        float s = 0.f;
#pragma unroll
        for (int g = 0; g < 8; g++) s += CP[g * 64 + tid];
        atomicAdd(&g_colsum[tid], s);
    }
}

// ---------------------------------------------------------------------------
// K6: finalize
// ---------------------------------------------------------------------------
__global__ void k_final(const int* __restrict__ counts,
                        const float* __restrict__ devx,
                        const float* __restrict__ timex,
                        const float* __restrict__ devW,
                        const float* __restrict__ devb,
                        float* __restrict__ out) {
    int tid = threadIdx.x;
    if (tid < 64) {
        int c = counts[0];
        if (c < 1) c = 1;
        out[tid] = g_colsum[tid] / (float)c;
    } else if (tid < 128) {
        int j = tid - 64;
        float p = devb[j];
#pragma unroll 8
        for (int k = 0; k < 96; k++) p += devx[k] * devW[k * 64 + j];
        p += (timex[0] * 1e-5f) * devW[96 * 64 + j];
        out[128 + j] = leaky(p);
    }
}

// ---------------------------------------------------------------------------
// Launch. k_gemm_tc stays at slot 4 (the ncu-profiled launch).
// ---------------------------------------------------------------------------
extern "C" void kernel_launch(void* const* d_in, const int* in_sizes, int n_in,
                              void* d_out, int out_size) {
    const float* data_x    = (const float*)d_in[0];
    const float* tasks_x   = (const float*)d_in[1];
    const float* devices_x = (const float*)d_in[2];
    const float* time_x    = (const float*)d_in[3];
    const int*   dt_src    = (const int*)d_in[4];
    const int*   dt_dst    = (const int*)d_in[5];
    const int*   tt_src    = (const int*)d_in[6];
    const int*   tt_dst    = (const int*)d_in[7];
    const int*   counts    = (const int*)d_in[8];
    const float* gcWrel    = (const float*)d_in[9];
    const float* gcbrel    = (const float*)d_in[10];
    const float* gcWroot   = (const float*)d_in[11];
    const float* gclng     = (const float*)d_in[12];
    const float* gclnb     = (const float*)d_in[13];
    const float* depW1     = (const float*)d_in[14];
    const float* depb1     = (const float*)d_in[15];
    const float* depW2     = (const float*)d_in[16];
    const float* depb2     = (const float*)d_in[17];
    const float* deplng    = (const float*)d_in[18];
    const float* deplnb    = (const float*)d_in[19];
    const float* revW1     = (const float*)d_in[20];
    const float* revb1     = (const float*)d_in[21];
    const float* revW2     = (const float*)d_in[22];
    const float* revb2     = (const float*)d_in[23];
    const float* revlng    = (const float*)d_in[24];
    const float* revlnb    = (const float*)d_in[25];
    const float* devW      = (const float*)d_in[26];
    const float* devb      = (const float*)d_in[27];
    const float* projW     = (const float*)d_in[28];
    const float* projb     = (const float*)d_in[29];
    float* out = (float*)d_out;

    int n    = in_sizes[1] / 12;
    int e_dt = in_sizes[4];
    int e_tt = in_sizes[6];
    int nblk = (n + 1023) / 1024;
    int emax = e_dt > e_tt ? e_dt : e_tt;

    cudaFuncSetAttribute(k_gemm_tc, cudaFuncAttributeMaxDynamicSharedMemorySize, 71680);
    cudaFuncSetAttribute(k_tail2,   cudaFuncAttributeMaxDynamicSharedMemorySize, 111360);

    int gb = (n + 127) / 128;

    k_zero<<<(n * 8 + 255) / 256, 256>>>(n);                                     // 1
    k_edges_pre<<<(emax + 255) / 256, 256>>>(data_x, dt_src, dt_dst, e_dt,
                                             tt_src, tt_dst, e_tt);              // 2
    k_fused<<<(n * 32 + 255) / 256, 256>>>(tasks_x, gcWrel, gcbrel, gcWroot,
                                           gclng, gclnb, n);                     // 3
    dim3 gg(gb, 2);
    k_gemm_tc<<<gg, 256, 71680>>>(depW1, revW1, n);                              // 4 <- profiled

    dim3 sg(nblk, 2);
    k_scan_blk<<<sg, 256>>>(n);                                                  // 5
    k_scan_top<<<1, 64>>>(nblk);                                                 // 6
    k_scan_fix<<<sg, 256>>>(n, e_tt);                                            // 7
    k_scatter<<<(e_tt + 255) / 256, 256>>>(tt_src, tt_dst, e_tt);                // 8

    dim3 ag((n + 7) / 8, 2);
    k_agg<<<ag, 256>>>(depb1, revb1, n);                                         // 9

    k_tail2<<<gb, 256, 111360>>>(depW2, depb2, deplng, deplnb,
                                 revW2, revb2, revlng, revlnb,
                                 projW, projb, out, n);                          // 10
    k_final<<<1, 128>>>(counts, devices_x, time_x, devW, devb, out);             // 11
}